// round 13
// baseline (speedup 1.0000x reference)
#include <cuda_runtime.h>
#include <cstdint>

#define EPSV 1e-5f
#define N_MAX   163904      // >= N+1 rows (N = 160000)
#define NP_MAX  65792       // >= NPOOL+1 rows

// -------- persistent scratch (no allocs allowed) --------
__device__ float g_x1[(size_t)N_MAX * 64];
__device__ float g_x2[(size_t)N_MAX * 64];
__device__ float g_xp[(size_t)NP_MAX * 64];
__device__ float g_y3[(size_t)NP_MAX * 128];
__device__ int   g_nbr [(size_t)N_MAX * 27];
__device__ int   g_nbr2[(size_t)NP_MAX * 27];
__device__ float g_stats[768];

typedef unsigned long long u64t;

__device__ __forceinline__ u64t pack2(float a, float b) {
    u64t r; unsigned x = __float_as_uint(a), y = __float_as_uint(b);
    asm("mov.b64 %0, {%1, %2};" : "=l"(r) : "r"(x), "r"(y));
    return r;
}
__device__ __forceinline__ void fma2(u64t& d, u64t a, u64t b) {
    asm("fma.rn.f32x2 %0, %1, %2, %0;" : "+l"(d) : "l"(a), "l"(b));
}
__device__ __forceinline__ float2 unpack2(u64t v) {
    unsigned lo, hi; asm("mov.b64 {%0, %1}, %2;" : "=r"(lo), "=r"(hi) : "l"(v));
    return make_float2(__uint_as_float(lo), __uint_as_float(hi));
}
__device__ __forceinline__ void redadd4(float* p, float4 v) {
    asm volatile("red.global.add.v4.f32 [%0], {%1,%2,%3,%4};"
                 :: "l"(p), "f"(v.x), "f"(v.y), "f"(v.z), "f"(v.w) : "memory");
}

// ---------------------------------------------------------------- init (stats, sentinels, zero x2/xp)
__global__ void initbig_kernel(int* __restrict__ nbr, int* __restrict__ nbr2,
                               float* __restrict__ xp, float* __restrict__ x2,
                               float* __restrict__ stats, int N, int NP) {
    int i = blockIdx.x * blockDim.x + threadIdx.x;
    if (i < 768) stats[i] = 0.f;
    if (i < 27 * N) nbr[i] = N;
    if (i < 27 * NP) nbr2[i] = NP;
    if (i < (NP + 1) * 64) xp[i] = 0.f;
    if (i < (N + 1) * 64) x2[i] = 0.f;
}
__global__ void build_nbr_kernel(const int* __restrict__ km_in, const int* __restrict__ km_out,
                                 int* __restrict__ nbr, int M, int Nr) {
    int idx = blockIdx.x * blockDim.x + threadIdx.x;
    if (idx >= 27 * M) return;
    int i = km_in[idx];
    if (i < Nr) {
        int k = idx / M;
        nbr[k * Nr + km_out[idx]] = i;
    }
}

// ---------------------------------------------------------------- conv1: 1 -> 64 channels, fused stats
__global__ void __launch_bounds__(256) conv1_kernel(const float* __restrict__ feats,
                                                    const float* __restrict__ W1,
                                                    float* __restrict__ out,
                                                    const int* __restrict__ nbr, int Nr,
                                                    float* __restrict__ stats) {
    __shared__ float fs[27 * 64];
    __shared__ float ws[27 * 64];
    __shared__ float sh[512];
    int t = threadIdx.x;
    int r0 = blockIdx.x * 64;
    for (int i = t; i < 27 * 64; i += 256) ws[i] = W1[i];
    for (int i = t; i < 27 * 64; i += 256) {
        int k = i >> 6, rr = i & 63, r = r0 + rr;
        float v = 0.f;
        if (r < Nr) {
            int g = nbr[k * Nr + r];
            if (g < Nr) v = feats[g];
        }
        fs[i] = v;
    }
    __syncthreads();
    int c = t & 63, rg = t >> 6;
    float s = 0.f, q = 0.f;
    #pragma unroll
    for (int ri = 0; ri < 16; ri++) {
        int rr = rg * 16 + ri, r = r0 + rr;
        if (r < Nr) {
            float acc = 0.f;
            #pragma unroll
            for (int k = 0; k < 27; k++) acc += fs[k * 64 + rr] * ws[k * 64 + c];
            out[(size_t)r * 64 + c] = acc;
            s += acc; q = fmaf(acc, acc, q);
        }
    }
    sh[t] = s; sh[256 + t] = q;
    __syncthreads();
    if (rg == 0) {
        #pragma unroll
        for (int g = 1; g < 4; g++) { s += sh[g * 64 + c]; q += sh[256 + g * 64 + c]; }
        atomicAdd(&stats[c], s);
        atomicAdd(&stats[128 + c], q);
    }
}

// ---------------------------------------------------------------- conv2: valid-pair scatter GEMM (256 pairs/block, 2 CTAs/SM — R8 config)
__global__ void __launch_bounds__(256, 2) conv2_scatter_kernel(
    const float* __restrict__ x1, const float* __restrict__ W2,
    float* __restrict__ x2,
    const int* __restrict__ km_in, const int* __restrict__ km_out,
    int M, int Nf,
    const float* __restrict__ sums, const float* __restrict__ sqs,
    const float* __restrict__ gam, const float* __restrict__ bet, float invn)
{
    const int k = blockIdx.y;
    const int p0 = blockIdx.x * 256;
    if (__ldg(km_in + (size_t)k * M + p0) >= Nf) return;   // front-packed: all-sentinel chunk

    extern __shared__ char smraw[];
    u64t* Xs = (u64t*)smraw;               // [64][128] row-pairs
    u64t* Wd = Xs + 64 * 128;              // [64][64]  duplicated weights
    float* bnc = (float*)(Wd + 64 * 64);   // mu[64], scl[64], be[64]

    const int t = threadIdx.x;
    const int tx = t & 15, ty = t >> 4;

    if (t < 64) {
        float mu = sums[t] * invn;
        float var = fmaf(-mu, mu, sqs[t] * invn);
        bnc[t] = mu;
        bnc[64 + t] = gam[t] * rsqrtf(var + EPSV);
        bnc[128 + t] = bet[t];
    }
    __syncthreads();

    // ---- gather 2 pair-rows per thread, 32 channels per half
    {
        const int grp = t & 127;
        const int j0 = (t >> 7) * 32;
        const int ra = p0 + 2 * grp, rb = ra + 1;
        int ga = (ra < M) ? __ldg(km_in + (size_t)k * M + ra) : Nf;
        int gb = (rb < M) ? __ldg(km_in + (size_t)k * M + rb) : Nf;
        const bool va = ga < Nf, vb = gb < Nf;
        const float4* pa = (const float4*)(x1 + (size_t)ga * 64) + (j0 >> 2);
        const float4* pb = (const float4*)(x1 + (size_t)gb * 64) + (j0 >> 2);
        #pragma unroll
        for (int q = 0; q < 8; q++) {
            float4 A = make_float4(0.f, 0.f, 0.f, 0.f), B = A;
            float4 mu = ((const float4*)bnc)[(j0 >> 2) + q];
            float4 sc = ((const float4*)(bnc + 64))[(j0 >> 2) + q];
            float4 be = ((const float4*)(bnc + 128))[(j0 >> 2) + q];
            if (va) {
                float4 v = pa[q];
                A.x = fmaxf(fmaf(v.x - mu.x, sc.x, be.x), 0.f);
                A.y = fmaxf(fmaf(v.y - mu.y, sc.y, be.y), 0.f);
                A.z = fmaxf(fmaf(v.z - mu.z, sc.z, be.z), 0.f);
                A.w = fmaxf(fmaf(v.w - mu.w, sc.w, be.w), 0.f);
            }
            if (vb) {
                float4 v = pb[q];
                B.x = fmaxf(fmaf(v.x - mu.x, sc.x, be.x), 0.f);
                B.y = fmaxf(fmaf(v.y - mu.y, sc.y, be.y), 0.f);
                B.z = fmaxf(fmaf(v.z - mu.z, sc.z, be.z), 0.f);
                B.w = fmaxf(fmaf(v.w - mu.w, sc.w, be.w), 0.f);
            }
            int j = j0 + 4 * q;
            Xs[(j + 0) * 128 + grp] = pack2(A.x, B.x);
            Xs[(j + 1) * 128 + grp] = pack2(A.y, B.y);
            Xs[(j + 2) * 128 + grp] = pack2(A.z, B.z);
            Xs[(j + 3) * 128 + grp] = pack2(A.w, B.w);
        }
        // weights, duplicated
        const float4* wk = (const float4*)(W2 + (size_t)k * 4096);
        #pragma unroll
        for (int i = 0; i < 4; i++) {
            float4 wv = wk[t + i * 256];
            int fi = (t + i * 256) * 4;
            Wd[fi + 0] = pack2(wv.x, wv.x);
            Wd[fi + 1] = pack2(wv.y, wv.y);
            Wd[fi + 2] = pack2(wv.z, wv.z);
            Wd[fi + 3] = pack2(wv.w, wv.w);
        }
    }
    __syncthreads();

    // ---- compute: 64 channels x (8 row-pairs x 4 cols)
    u64t acc[8][4];
    #pragma unroll
    for (int i = 0; i < 8; i++)
        #pragma unroll
        for (int c = 0; c < 4; c++) acc[i][c] = 0ULL;

    #pragma unroll 4
    for (int j = 0; j < 64; j++) {
        const u64t* ap = Xs + j * 128 + ty * 8;
        const u64t* bp = Wd + j * 64 + tx * 4;
        u64t a0 = ap[0], a1 = ap[1], a2 = ap[2], a3 = ap[3];
        u64t a4 = ap[4], a5 = ap[5], a6 = ap[6], a7 = ap[7];
        u64t b0 = bp[0], b1 = bp[1], b2 = bp[2], b3 = bp[3];
        fma2(acc[0][0], a0, b0); fma2(acc[0][1], a0, b1); fma2(acc[0][2], a0, b2); fma2(acc[0][3], a0, b3);
        fma2(acc[1][0], a1, b0); fma2(acc[1][1], a1, b1); fma2(acc[1][2], a1, b2); fma2(acc[1][3], a1, b3);
        fma2(acc[2][0], a2, b0); fma2(acc[2][1], a2, b1); fma2(acc[2][2], a2, b2); fma2(acc[2][3], a2, b3);
        fma2(acc[3][0], a3, b0); fma2(acc[3][1], a3, b1); fma2(acc[3][2], a3, b2); fma2(acc[3][3], a3, b3);
        fma2(acc[4][0], a4, b0); fma2(acc[4][1], a4, b1); fma2(acc[4][2], a4, b2); fma2(acc[4][3], a4, b3);
        fma2(acc[5][0], a5, b0); fma2(acc[5][1], a5, b1); fma2(acc[5][2], a5, b2); fma2(acc[5][3], a5, b3);
        fma2(acc[6][0], a6, b0); fma2(acc[6][1], a6, b1); fma2(acc[6][2], a6, b2); fma2(acc[6][3], a6, b3);
        fma2(acc[7][0], a7, b0); fma2(acc[7][1], a7, b1); fma2(acc[7][2], a7, b2); fma2(acc[7][3], a7, b3);
    }

    // ---- scatter epilogue: v4 vector reds, skip sentinels
    #pragma unroll
    for (int i = 0; i < 8; i++) {
        int pr = p0 + ty * 16 + 2 * i;
        int oa = (pr < M) ? __ldg(km_out + (size_t)k * M + pr) : Nf;
        int ob = (pr + 1 < M) ? __ldg(km_out + (size_t)k * M + pr + 1) : Nf;
        float2 e0 = unpack2(acc[i][0]), e1 = unpack2(acc[i][1]);
        float2 e2 = unpack2(acc[i][2]), e3 = unpack2(acc[i][3]);
        if (oa < Nf)
            redadd4(x2 + (size_t)oa * 64 + tx * 4, make_float4(e0.x, e1.x, e2.x, e3.x));
        if (ob < Nf)
            redadd4(x2 + (size_t)ob * 64 + tx * 4, make_float4(e0.y, e1.y, e2.y, e3.y));
    }
}

// ---------------------------------------------------------------- conv3: dense gather 64 rows x 128 cols, 2 CTAs/SM,
// W pre-duplicated in smem (no pack movs in inner loop), X register prefetch (no W prefetch -> no spills)
__global__ void __launch_bounds__(256, 2) conv3_kernel(
    const float* __restrict__ x, const float* __restrict__ W,
    float* __restrict__ out, const int* __restrict__ nbr, int Nr,
    float* __restrict__ oS, float* __restrict__ oQ)
{
    extern __shared__ char smraw[];
    u64t* Xs = (u64t*)smraw;              // [64 j][32 row-pairs]  (16 KB)
    u64t* Wd = Xs + 64 * 32;              // [64 j][128 c] duplicated (64 KB)
    float* redS = (float*)(Wd + 64 * 128);
    float* redQ = redS + 128;

    const int t = threadIdx.x;
    const int tx = t & 31, ty = t >> 5;   // warp-uniform ty
    const int r0 = blockIdx.x * 64;
    const int grp = t & 31;
    const int j0 = (t >> 5) * 8;

    if (t < 128) { redS[t] = 0.f; redQ[t] = 0.f; }

    u64t acc[4][4];
    #pragma unroll
    for (int i = 0; i < 4; i++)
        #pragma unroll
        for (int c = 0; c < 4; c++) acc[i][c] = 0ULL;

    const int ra = r0 + 2 * grp, rb = ra + 1;

    float4 xpre[4];   // 2 gathered rows x 8 floats (16 regs)

    auto ldg_x = [&](int k) {
        int ga = (ra < Nr) ? __ldg(nbr + (size_t)k * Nr + ra) : Nr;
        int gb = (rb < Nr) ? __ldg(nbr + (size_t)k * Nr + rb) : Nr;
        const float4* pa = (const float4*)(x + (size_t)ga * 64) + (j0 >> 2);
        const float4* pb = (const float4*)(x + (size_t)gb * 64) + (j0 >> 2);
        xpre[0] = pa[0]; xpre[1] = pa[1];
        xpre[2] = pb[0]; xpre[3] = pb[1];
    };

    ldg_x(0);   // prologue

    for (int k = 0; k < 27; k++) {
        __syncthreads();    // previous compute done; Xs/Wd free
        // STS prefetched X (pack row pairs)
        #pragma unroll
        for (int q = 0; q < 2; q++) {
            float4 va = xpre[q], vb = xpre[2 + q];
            int j = j0 + 4 * q;
            Xs[(j + 0) * 32 + grp] = pack2(va.x, vb.x);
            Xs[(j + 1) * 32 + grp] = pack2(va.y, vb.y);
            Xs[(j + 2) * 32 + grp] = pack2(va.z, vb.z);
            Xs[(j + 3) * 32 + grp] = pack2(va.w, vb.w);
        }
        // W tile: LDG -> duplicate -> STS u64 (once per k, outside inner loop)
        const float4* wk = (const float4*)(W + (size_t)k * 8192);
        #pragma unroll
        for (int i = 0; i < 8; i++) {
            float4 wv = wk[t + i * 256];
            int fi = (t + i * 256) * 4;    // linear = j*128 + c
            Wd[fi + 0] = pack2(wv.x, wv.x);
            Wd[fi + 1] = pack2(wv.y, wv.y);
            Wd[fi + 2] = pack2(wv.z, wv.z);
            Wd[fi + 3] = pack2(wv.w, wv.w);
        }
        __syncthreads();

        if (k < 26) ldg_x(k + 1);   // X gather chain for k+1 in flight under compute(k)

        #pragma unroll 4
        for (int j = 0; j < 64; j++) {
            const u64t* ap = Xs + j * 32 + ty * 4;
            const u64t* bp = Wd + j * 128 + tx * 4;
            u64t a0 = ap[0], a1 = ap[1], a2 = ap[2], a3 = ap[3];
            u64t b0 = bp[0], b1 = bp[1], b2 = bp[2], b3 = bp[3];
            fma2(acc[0][0], a0, b0); fma2(acc[0][1], a0, b1); fma2(acc[0][2], a0, b2); fma2(acc[0][3], a0, b3);
            fma2(acc[1][0], a1, b0); fma2(acc[1][1], a1, b1); fma2(acc[1][2], a1, b2); fma2(acc[1][3], a1, b3);
            fma2(acc[2][0], a2, b0); fma2(acc[2][1], a2, b1); fma2(acc[2][2], a2, b2); fma2(acc[2][3], a2, b3);
            fma2(acc[3][0], a3, b0); fma2(acc[3][1], a3, b1); fma2(acc[3][2], a3, b2); fma2(acc[3][3], a3, b3);
        }
    }

    // ---- epilogue: store + fused BN stats partials
    float scol[4] = {0.f, 0.f, 0.f, 0.f}, qcol[4] = {0.f, 0.f, 0.f, 0.f};
    #pragma unroll
    for (int i = 0; i < 4; i++) {
        float2 e0 = unpack2(acc[i][0]), e1 = unpack2(acc[i][1]);
        float2 e2 = unpack2(acc[i][2]), e3 = unpack2(acc[i][3]);
        int re = r0 + ty * 8 + 2 * i;
        if (re < Nr) {
            *(float4*)(out + (size_t)re * 128 + tx * 4) = make_float4(e0.x, e1.x, e2.x, e3.x);
            scol[0] += e0.x; qcol[0] = fmaf(e0.x, e0.x, qcol[0]);
            scol[1] += e1.x; qcol[1] = fmaf(e1.x, e1.x, qcol[1]);
            scol[2] += e2.x; qcol[2] = fmaf(e2.x, e2.x, qcol[2]);
            scol[3] += e3.x; qcol[3] = fmaf(e3.x, e3.x, qcol[3]);
        }
        if (re + 1 < Nr) {
            *(float4*)(out + (size_t)(re + 1) * 128 + tx * 4) = make_float4(e0.y, e1.y, e2.y, e3.y);
            scol[0] += e0.y; qcol[0] = fmaf(e0.y, e0.y, qcol[0]);
            scol[1] += e1.y; qcol[1] = fmaf(e1.y, e1.y, qcol[1]);
            scol[2] += e2.y; qcol[2] = fmaf(e2.y, e2.y, qcol[2]);
            scol[3] += e3.y; qcol[3] = fmaf(e3.y, e3.y, qcol[3]);
        }
    }
    __syncthreads();
    #pragma unroll
    for (int c = 0; c < 4; c++) {
        atomicAdd(&redS[tx * 4 + c], scol[c]);
        atomicAdd(&redQ[tx * 4 + c], qcol[c]);
    }
    __syncthreads();
    if (t < 128) {
        atomicAdd(&oS[t], redS[t]);
        atomicAdd(&oQ[t], redQ[t]);
    }
}

// ---------------------------------------------------------------- BN reduce / apply / pool
template<int C>
__global__ void __launch_bounds__(256) bn_reduce_kernel(const float* __restrict__ x, int rows,
                                                        float* __restrict__ sumo, float* __restrict__ sqo) {
    constexpr int G = 256 / C;
    int t = threadIdx.x, c = t & (C - 1), rg = t / C;
    float s = 0.f, q = 0.f;
    for (int r = blockIdx.x * G + rg; r < rows; r += gridDim.x * G) {
        float v = x[(size_t)r * C + c];
        s += v; q = fmaf(v, v, q);
    }
    __shared__ float sh[512];
    sh[t] = s; sh[256 + t] = q;
    __syncthreads();
    if (rg == 0) {
        #pragma unroll
        for (int g = 1; g < G; g++) { s += sh[g * C + c]; q += sh[256 + g * C + c]; }
        atomicAdd(&sumo[c], s);
        atomicAdd(&sqo[c], q);
    }
}

__global__ void __launch_bounds__(256) bn_apply_pool_kernel(const float* __restrict__ x,
                                                            const int* __restrict__ seg,
                                                            float* __restrict__ xp, int rows,
                                                            const float* __restrict__ gam, const float* __restrict__ bet,
                                                            const float* __restrict__ sums, const float* __restrict__ sqs) {
    size_t total = (size_t)rows * 64;
    float invn = 1.f / (float)rows;
    for (size_t idx = (size_t)blockIdx.x * 256 + threadIdx.x; idx < total; idx += (size_t)gridDim.x * 256) {
        int c = (int)(idx & 63);
        int r = (int)(idx >> 6);
        float mu = sums[c] * invn;
        float var = fmaf(-mu, mu, sqs[c] * invn);
        float scl = gam[c] * rsqrtf(var + EPSV);
        float v = fmaxf(fmaf(x[idx] - mu, scl, bet[c]), 0.f);
        atomicMax((unsigned int*)&xp[(size_t)seg[r] * 64 + c], __float_as_uint(v));
    }
}

template<int C>
__global__ void __launch_bounds__(256) bn_apply_kernel(const float* __restrict__ x, float* __restrict__ y,
                                                       int rows,
                                                       const float* __restrict__ gam, const float* __restrict__ bet,
                                                       const float* __restrict__ sums, const float* __restrict__ sqs) {
    size_t total = (size_t)rows * C;
    float invn = 1.f / (float)rows;
    for (size_t idx = (size_t)blockIdx.x * 256 + threadIdx.x; idx < total; idx += (size_t)gridDim.x * 256) {
        int c = (int)(idx & (C - 1));
        float mu = sums[c] * invn;
        float var = fmaf(-mu, mu, sqs[c] * invn);
        float scl = gam[c] * rsqrtf(var + EPSV);
        float v = fmaf(x[idx] - mu, scl, bet[c]);
        y[idx] = fmaxf(v, 0.f);
    }
}

// ---------------------------------------------------------------- launch
extern "C" void kernel_launch(void* const* d_in, const int* in_sizes, int n_in,
                              void* d_out, int out_size) {
    const float* feats = (const float*)d_in[0];
    const float* W1    = (const float*)d_in[1];
    const float* g1    = (const float*)d_in[3];
    const float* be1   = (const float*)d_in[4];
    const float* W2    = (const float*)d_in[5];
    const float* g2    = (const float*)d_in[7];
    const float* be2   = (const float*)d_in[8];
    const float* W3    = (const float*)d_in[9];
    const float* g3    = (const float*)d_in[11];
    const float* be3   = (const float*)d_in[12];
    const int* km_in   = (const int*)d_in[13];
    const int* km_out  = (const int*)d_in[14];
    const int* seg     = (const int*)d_in[15];
    const int* km2_in  = (const int*)d_in[16];
    const int* km2_out = (const int*)d_in[17];

    int N  = in_sizes[0];
    int M  = in_sizes[13] / 27;
    int M2 = in_sizes[16] / 27;
    int NP = out_size / 128;

    float *x1, *x2, *xp, *y3, *stats; int *nbr, *nbr2;
    cudaGetSymbolAddress((void**)&x1, g_x1);
    cudaGetSymbolAddress((void**)&x2, g_x2);
    cudaGetSymbolAddress((void**)&xp, g_xp);
    cudaGetSymbolAddress((void**)&y3, g_y3);
    cudaGetSymbolAddress((void**)&nbr, g_nbr);
    cudaGetSymbolAddress((void**)&nbr2, g_nbr2);
    cudaGetSymbolAddress((void**)&stats, g_stats);

    constexpr int SM2 = (64 * 128 + 64 * 64) * 8 + 192 * 4;             // 99072 (R8 config)
    constexpr int SM3 = 64 * 32 * 8 + 64 * 128 * 8 + 2 * 128 * 4;       // 82944 (Wd dup)
    cudaFuncSetAttribute((const void*)conv2_scatter_kernel,
                         cudaFuncAttributeMaxDynamicSharedMemorySize, SM2);
    cudaFuncSetAttribute((const void*)conv3_kernel,
                         cudaFuncAttributeMaxDynamicSharedMemorySize, SM3);

    int initThreads = (N + 1) * 64;
    if (27 * N > initThreads) initThreads = 27 * N;

    // (1) init: stats, sentinel tables, zero xp & x2
    initbig_kernel<<<(initThreads + 255) / 256, 256>>>(nbr, nbr2, xp, x2, stats, N, NP);
    // (2) neighbor table for layer 1 dense gather
    build_nbr_kernel<<<(27 * M + 255) / 256, 256>>>(km_in, km_out, nbr, M, N);
    // (3) conv1 + fused stats1
    conv1_kernel<<<(N + 63) / 64, 256>>>(feats, W1, x1, nbr, N, stats);
    // (4) conv2 scatter, 256-pair blocks, 2 CTAs/SM     <-- ncu capture target
    {
        dim3 grid((M + 255) / 256, 27);
        conv2_scatter_kernel<<<grid, 256, SM2>>>(
            x1, W2, x2, km_in, km_out, M, N,
            stats + 0, stats + 128, g1, be1, 1.f / (float)N);
    }
    // (5) neighbor table for layer 3
    build_nbr_kernel<<<(27 * M2 + 255) / 256, 256>>>(km2_in, km2_out, nbr2, M2, NP);
    // (6) BN2 stats
    bn_reduce_kernel<64><<<592, 256>>>(x2, N, stats + 256, stats + 384);
    // (7) BN2+ReLU fused with maxpool
    bn_apply_pool_kernel<<<1184, 256>>>(x2, seg, xp, N, g2, be2, stats + 256, stats + 384);
    // (8) conv3 dense, Wd pre-duplicated, X prefetch, 2 CTAs/SM + fused stats3
    conv3_kernel<<<(NP + 63) / 64, 256, SM3>>>(
        xp, W3, y3, nbr2, NP, stats + 512, stats + 640);
    // (9) BN3+ReLU -> output
    bn_apply_kernel<128><<<1184, 256>>>(y3, (float*)d_out, NP, g3, be3, stats + 512, stats + 640);
}

// round 14
// speedup vs baseline: 1.0243x; 1.0243x over previous
#include <cuda_runtime.h>
#include <cstdint>

#define EPSV 1e-5f
#define N_MAX   163904      // >= N+1 rows (N = 160000)
#define NP_MAX  65792       // >= NPOOL+1 rows

// -------- persistent scratch (no allocs allowed) --------
__device__ float g_x1[(size_t)N_MAX * 64];
__device__ float g_x2[(size_t)N_MAX * 64];
__device__ float g_xp[(size_t)NP_MAX * 64];
__device__ float g_y3[(size_t)NP_MAX * 128];
__device__ int   g_nbr [(size_t)N_MAX * 27];
__device__ int   g_nbr2[(size_t)NP_MAX * 27];
__device__ float g_stats[768];

typedef unsigned long long u64t;

__device__ __forceinline__ u64t pack2(float a, float b) {
    u64t r; unsigned x = __float_as_uint(a), y = __float_as_uint(b);
    asm("mov.b64 %0, {%1, %2};" : "=l"(r) : "r"(x), "r"(y));
    return r;
}
__device__ __forceinline__ void fma2(u64t& d, u64t a, u64t b) {
    asm("fma.rn.f32x2 %0, %1, %2, %0;" : "+l"(d) : "l"(a), "l"(b));
}
__device__ __forceinline__ float2 unpack2(u64t v) {
    unsigned lo, hi; asm("mov.b64 {%0, %1}, %2;" : "=r"(lo), "=r"(hi) : "l"(v));
    return make_float2(__uint_as_float(lo), __uint_as_float(hi));
}
__device__ __forceinline__ void redadd4(float* p, float4 v) {
    asm volatile("red.global.add.v4.f32 [%0], {%1,%2,%3,%4};"
                 :: "l"(p), "f"(v.x), "f"(v.y), "f"(v.z), "f"(v.w) : "memory");
}

// ---------------------------------------------------------------- init (stats, sentinels, zero x2/xp)
__global__ void initbig_kernel(int* __restrict__ nbr, int* __restrict__ nbr2,
                               float* __restrict__ xp, float* __restrict__ x2,
                               float* __restrict__ stats, int N, int NP) {
    int i = blockIdx.x * blockDim.x + threadIdx.x;
    if (i < 768) stats[i] = 0.f;
    if (i < 27 * N) nbr[i] = N;
    if (i < 27 * NP) nbr2[i] = NP;
    if (i < (NP + 1) * 64) xp[i] = 0.f;
    if (i < (N + 1) * 64) x2[i] = 0.f;
}
__global__ void build_nbr_kernel(const int* __restrict__ km_in, const int* __restrict__ km_out,
                                 int* __restrict__ nbr, int M, int Nr) {
    int idx = blockIdx.x * blockDim.x + threadIdx.x;
    if (idx >= 27 * M) return;
    int i = km_in[idx];
    if (i < Nr) {
        int k = idx / M;
        nbr[k * Nr + km_out[idx]] = i;
    }
}

// ---------------------------------------------------------------- conv1: 1 -> 64 channels, fused stats
__global__ void __launch_bounds__(256) conv1_kernel(const float* __restrict__ feats,
                                                    const float* __restrict__ W1,
                                                    float* __restrict__ out,
                                                    const int* __restrict__ nbr, int Nr,
                                                    float* __restrict__ stats) {
    __shared__ float fs[27 * 64];
    __shared__ float ws[27 * 64];
    __shared__ float sh[512];
    int t = threadIdx.x;
    int r0 = blockIdx.x * 64;
    for (int i = t; i < 27 * 64; i += 256) ws[i] = W1[i];
    for (int i = t; i < 27 * 64; i += 256) {
        int k = i >> 6, rr = i & 63, r = r0 + rr;
        float v = 0.f;
        if (r < Nr) {
            int g = nbr[k * Nr + r];
            if (g < Nr) v = feats[g];
        }
        fs[i] = v;
    }
    __syncthreads();
    int c = t & 63, rg = t >> 6;
    float s = 0.f, q = 0.f;
    #pragma unroll
    for (int ri = 0; ri < 16; ri++) {
        int rr = rg * 16 + ri, r = r0 + rr;
        if (r < Nr) {
            float acc = 0.f;
            #pragma unroll
            for (int k = 0; k < 27; k++) acc += fs[k * 64 + rr] * ws[k * 64 + c];
            out[(size_t)r * 64 + c] = acc;
            s += acc; q = fmaf(acc, acc, q);
        }
    }
    sh[t] = s; sh[256 + t] = q;
    __syncthreads();
    if (rg == 0) {
        #pragma unroll
        for (int g = 1; g < 4; g++) { s += sh[g * 64 + c]; q += sh[256 + g * 64 + c]; }
        atomicAdd(&stats[c], s);
        atomicAdd(&stats[128 + c], q);
    }
}

// ---------------------------------------------------------------- conv2: valid-pair scatter GEMM (256 pairs/block, 2 CTAs/SM — R8 config)
__global__ void __launch_bounds__(256, 2) conv2_scatter_kernel(
    const float* __restrict__ x1, const float* __restrict__ W2,
    float* __restrict__ x2,
    const int* __restrict__ km_in, const int* __restrict__ km_out,
    int M, int Nf,
    const float* __restrict__ sums, const float* __restrict__ sqs,
    const float* __restrict__ gam, const float* __restrict__ bet, float invn)
{
    const int k = blockIdx.y;
    const int p0 = blockIdx.x * 256;
    if (__ldg(km_in + (size_t)k * M + p0) >= Nf) return;   // front-packed: all-sentinel chunk

    extern __shared__ char smraw[];
    u64t* Xs = (u64t*)smraw;               // [64][128] row-pairs
    u64t* Wd = Xs + 64 * 128;              // [64][64]  duplicated weights
    float* bnc = (float*)(Wd + 64 * 64);   // mu[64], scl[64], be[64]

    const int t = threadIdx.x;
    const int tx = t & 15, ty = t >> 4;

    if (t < 64) {
        float mu = sums[t] * invn;
        float var = fmaf(-mu, mu, sqs[t] * invn);
        bnc[t] = mu;
        bnc[64 + t] = gam[t] * rsqrtf(var + EPSV);
        bnc[128 + t] = bet[t];
    }
    __syncthreads();

    // ---- gather 2 pair-rows per thread, 32 channels per half
    {
        const int grp = t & 127;
        const int j0 = (t >> 7) * 32;
        const int ra = p0 + 2 * grp, rb = ra + 1;
        int ga = (ra < M) ? __ldg(km_in + (size_t)k * M + ra) : Nf;
        int gb = (rb < M) ? __ldg(km_in + (size_t)k * M + rb) : Nf;
        const bool va = ga < Nf, vb = gb < Nf;
        const float4* pa = (const float4*)(x1 + (size_t)ga * 64) + (j0 >> 2);
        const float4* pb = (const float4*)(x1 + (size_t)gb * 64) + (j0 >> 2);
        #pragma unroll
        for (int q = 0; q < 8; q++) {
            float4 A = make_float4(0.f, 0.f, 0.f, 0.f), B = A;
            float4 mu = ((const float4*)bnc)[(j0 >> 2) + q];
            float4 sc = ((const float4*)(bnc + 64))[(j0 >> 2) + q];
            float4 be = ((const float4*)(bnc + 128))[(j0 >> 2) + q];
            if (va) {
                float4 v = pa[q];
                A.x = fmaxf(fmaf(v.x - mu.x, sc.x, be.x), 0.f);
                A.y = fmaxf(fmaf(v.y - mu.y, sc.y, be.y), 0.f);
                A.z = fmaxf(fmaf(v.z - mu.z, sc.z, be.z), 0.f);
                A.w = fmaxf(fmaf(v.w - mu.w, sc.w, be.w), 0.f);
            }
            if (vb) {
                float4 v = pb[q];
                B.x = fmaxf(fmaf(v.x - mu.x, sc.x, be.x), 0.f);
                B.y = fmaxf(fmaf(v.y - mu.y, sc.y, be.y), 0.f);
                B.z = fmaxf(fmaf(v.z - mu.z, sc.z, be.z), 0.f);
                B.w = fmaxf(fmaf(v.w - mu.w, sc.w, be.w), 0.f);
            }
            int j = j0 + 4 * q;
            Xs[(j + 0) * 128 + grp] = pack2(A.x, B.x);
            Xs[(j + 1) * 128 + grp] = pack2(A.y, B.y);
            Xs[(j + 2) * 128 + grp] = pack2(A.z, B.z);
            Xs[(j + 3) * 128 + grp] = pack2(A.w, B.w);
        }
        // weights, duplicated
        const float4* wk = (const float4*)(W2 + (size_t)k * 4096);
        #pragma unroll
        for (int i = 0; i < 4; i++) {
            float4 wv = wk[t + i * 256];
            int fi = (t + i * 256) * 4;
            Wd[fi + 0] = pack2(wv.x, wv.x);
            Wd[fi + 1] = pack2(wv.y, wv.y);
            Wd[fi + 2] = pack2(wv.z, wv.z);
            Wd[fi + 3] = pack2(wv.w, wv.w);
        }
    }
    __syncthreads();

    // ---- compute: 64 channels x (8 row-pairs x 4 cols)
    u64t acc[8][4];
    #pragma unroll
    for (int i = 0; i < 8; i++)
        #pragma unroll
        for (int c = 0; c < 4; c++) acc[i][c] = 0ULL;

    #pragma unroll 4
    for (int j = 0; j < 64; j++) {
        const u64t* ap = Xs + j * 128 + ty * 8;
        const u64t* bp = Wd + j * 64 + tx * 4;
        u64t a0 = ap[0], a1 = ap[1], a2 = ap[2], a3 = ap[3];
        u64t a4 = ap[4], a5 = ap[5], a6 = ap[6], a7 = ap[7];
        u64t b0 = bp[0], b1 = bp[1], b2 = bp[2], b3 = bp[3];
        fma2(acc[0][0], a0, b0); fma2(acc[0][1], a0, b1); fma2(acc[0][2], a0, b2); fma2(acc[0][3], a0, b3);
        fma2(acc[1][0], a1, b0); fma2(acc[1][1], a1, b1); fma2(acc[1][2], a1, b2); fma2(acc[1][3], a1, b3);
        fma2(acc[2][0], a2, b0); fma2(acc[2][1], a2, b1); fma2(acc[2][2], a2, b2); fma2(acc[2][3], a2, b3);
        fma2(acc[3][0], a3, b0); fma2(acc[3][1], a3, b1); fma2(acc[3][2], a3, b2); fma2(acc[3][3], a3, b3);
        fma2(acc[4][0], a4, b0); fma2(acc[4][1], a4, b1); fma2(acc[4][2], a4, b2); fma2(acc[4][3], a4, b3);
        fma2(acc[5][0], a5, b0); fma2(acc[5][1], a5, b1); fma2(acc[5][2], a5, b2); fma2(acc[5][3], a5, b3);
        fma2(acc[6][0], a6, b0); fma2(acc[6][1], a6, b1); fma2(acc[6][2], a6, b2); fma2(acc[6][3], a6, b3);
        fma2(acc[7][0], a7, b0); fma2(acc[7][1], a7, b1); fma2(acc[7][2], a7, b2); fma2(acc[7][3], a7, b3);
    }

    // ---- scatter epilogue: v4 vector reds, skip sentinels
    #pragma unroll
    for (int i = 0; i < 8; i++) {
        int pr = p0 + ty * 16 + 2 * i;
        int oa = (pr < M) ? __ldg(km_out + (size_t)k * M + pr) : Nf;
        int ob = (pr + 1 < M) ? __ldg(km_out + (size_t)k * M + pr + 1) : Nf;
        float2 e0 = unpack2(acc[i][0]), e1 = unpack2(acc[i][1]);
        float2 e2 = unpack2(acc[i][2]), e3 = unpack2(acc[i][3]);
        if (oa < Nf)
            redadd4(x2 + (size_t)oa * 64 + tx * 4, make_float4(e0.x, e1.x, e2.x, e3.x));
        if (ob < Nf)
            redadd4(x2 + (size_t)ob * 64 + tx * 4, make_float4(e0.y, e1.y, e2.y, e3.y));
    }
}

// ---------------------------------------------------------------- conv3: dense gather 64 rows x 128 cols, 3 CTAs/SM
// Transposed duplication: X stored duplicated (u64), W read as natural col-pairs -> zero movs in inner loop.
__global__ void __launch_bounds__(256, 3) conv3_kernel(
    const float* __restrict__ x, const float* __restrict__ W,
    float* __restrict__ out, const int* __restrict__ nbr, int Nr,
    float* __restrict__ oS, float* __restrict__ oQ)
{
    extern __shared__ char smraw[];
    u64t* Xd = (u64t*)smraw;              // [64 j][64 rows] duplicated x (32 KB)
    float* Ws = (float*)(Xd + 64 * 64);   // [64 j][128 c] plain floats (32 KB)
    float* redS = Ws + 64 * 128;
    float* redQ = redS + 128;

    const int t = threadIdx.x;
    const int tx = t & 15, ty = t >> 4;   // tx: 8 cols (tx*8..+7), ty: 4 rows (ty*4..+3)
    const int r0 = blockIdx.x * 64;
    const int grow = t & 63;              // gathered row (4 threads per row)
    const int j0 = (t >> 6) * 16;         // channel chunk

    if (t < 128) { redS[t] = 0.f; redQ[t] = 0.f; }

    u64t acc[4][4];                        // [row i][col-pair cc]
    #pragma unroll
    for (int i = 0; i < 4; i++)
        #pragma unroll
        for (int c = 0; c < 4; c++) acc[i][c] = 0ULL;

    const int ra = r0 + grow;

    float4 xpre[4];   // 16 channels of the gathered row

    auto ldg_x = [&](int k) {
        int g = (ra < Nr) ? __ldg(nbr + (size_t)k * Nr + ra) : Nr;
        const float4* p = (const float4*)(x + (size_t)g * 64) + (j0 >> 2);
        xpre[0] = p[0]; xpre[1] = p[1]; xpre[2] = p[2]; xpre[3] = p[3];
    };

    ldg_x(0);   // prologue

    for (int k = 0; k < 27; k++) {
        __syncthreads();    // previous compute done; Xd/Ws free
        // STS prefetched X, duplicated per element
        #pragma unroll
        for (int q = 0; q < 4; q++) {
            float4 v = xpre[q];
            int j = j0 + 4 * q;
            Xd[(j + 0) * 64 + grow] = pack2(v.x, v.x);
            Xd[(j + 1) * 64 + grow] = pack2(v.y, v.y);
            Xd[(j + 2) * 64 + grow] = pack2(v.z, v.z);
            Xd[(j + 3) * 64 + grow] = pack2(v.w, v.w);
        }
        // W tile: plain float4 copy
        const float4* wk = (const float4*)(W + (size_t)k * 8192);
        #pragma unroll
        for (int i = 0; i < 8; i++)
            ((float4*)Ws)[t + i * 256] = wk[t + i * 256];
        __syncthreads();

        if (k < 26) ldg_x(k + 1);   // gather chain for k+1 under compute(k)

        #pragma unroll 4
        for (int j = 0; j < 64; j++) {
            const u64t* ap = Xd + j * 64 + ty * 4;
            const u64t* bp = (const u64t*)(Ws + j * 128 + tx * 8);
            u64t a0 = ap[0], a1 = ap[1], a2 = ap[2], a3 = ap[3];
            u64t b0 = bp[0], b1 = bp[1], b2 = bp[2], b3 = bp[3];
            fma2(acc[0][0], a0, b0); fma2(acc[0][1], a0, b1); fma2(acc[0][2], a0, b2); fma2(acc[0][3], a0, b3);
            fma2(acc[1][0], a1, b0); fma2(acc[1][1], a1, b1); fma2(acc[1][2], a1, b2); fma2(acc[1][3], a1, b3);
            fma2(acc[2][0], a2, b0); fma2(acc[2][1], a2, b1); fma2(acc[2][2], a2, b2); fma2(acc[2][3], a2, b3);
            fma2(acc[3][0], a3, b0); fma2(acc[3][1], a3, b1); fma2(acc[3][2], a3, b2); fma2(acc[3][3], a3, b3);
        }
    }

    // ---- epilogue: acc[i][cc] = (out[r0+ty*4+i][tx*8+2cc], ..+1); store + fused stats
    float scol[8], qcol[8];
    #pragma unroll
    for (int c = 0; c < 8; c++) { scol[c] = 0.f; qcol[c] = 0.f; }
    #pragma unroll
    for (int i = 0; i < 4; i++) {
        int re = r0 + ty * 4 + i;
        if (re < Nr) {
            float2 e0 = unpack2(acc[i][0]), e1 = unpack2(acc[i][1]);
            float2 e2 = unpack2(acc[i][2]), e3 = unpack2(acc[i][3]);
            float* o = out + (size_t)re * 128 + tx * 8;
            *(float4*)(o + 0) = make_float4(e0.x, e0.y, e1.x, e1.y);
            *(float4*)(o + 4) = make_float4(e2.x, e2.y, e3.x, e3.y);
            float vs[8] = { e0.x, e0.y, e1.x, e1.y, e2.x, e2.y, e3.x, e3.y };
            #pragma unroll
            for (int c = 0; c < 8; c++) { scol[c] += vs[c]; qcol[c] = fmaf(vs[c], vs[c], qcol[c]); }
        }
    }
    __syncthreads();
    #pragma unroll
    for (int c = 0; c < 8; c++) {
        atomicAdd(&redS[tx * 8 + c], scol[c]);
        atomicAdd(&redQ[tx * 8 + c], qcol[c]);
    }
    __syncthreads();
    if (t < 128) {
        atomicAdd(&oS[t], redS[t]);
        atomicAdd(&oQ[t], redQ[t]);
    }
}

// ---------------------------------------------------------------- BN reduce / apply / pool
template<int C>
__global__ void __launch_bounds__(256) bn_reduce_kernel(const float* __restrict__ x, int rows,
                                                        float* __restrict__ sumo, float* __restrict__ sqo) {
    constexpr int G = 256 / C;
    int t = threadIdx.x, c = t & (C - 1), rg = t / C;
    float s = 0.f, q = 0.f;
    for (int r = blockIdx.x * G + rg; r < rows; r += gridDim.x * G) {
        float v = x[(size_t)r * C + c];
        s += v; q = fmaf(v, v, q);
    }
    __shared__ float sh[512];
    sh[t] = s; sh[256 + t] = q;
    __syncthreads();
    if (rg == 0) {
        #pragma unroll
        for (int g = 1; g < G; g++) { s += sh[g * C + c]; q += sh[256 + g * C + c]; }
        atomicAdd(&sumo[c], s);
        atomicAdd(&sqo[c], q);
    }
}

__global__ void __launch_bounds__(256) bn_apply_pool_kernel(const float* __restrict__ x,
                                                            const int* __restrict__ seg,
                                                            float* __restrict__ xp, int rows,
                                                            const float* __restrict__ gam, const float* __restrict__ bet,
                                                            const float* __restrict__ sums, const float* __restrict__ sqs) {
    size_t total = (size_t)rows * 64;
    float invn = 1.f / (float)rows;
    for (size_t idx = (size_t)blockIdx.x * 256 + threadIdx.x; idx < total; idx += (size_t)gridDim.x * 256) {
        int c = (int)(idx & 63);
        int r = (int)(idx >> 6);
        float mu = sums[c] * invn;
        float var = fmaf(-mu, mu, sqs[c] * invn);
        float scl = gam[c] * rsqrtf(var + EPSV);
        float v = fmaxf(fmaf(x[idx] - mu, scl, bet[c]), 0.f);
        atomicMax((unsigned int*)&xp[(size_t)seg[r] * 64 + c], __float_as_uint(v));
    }
}

// final BN apply, float4-vectorized (C=128)
__global__ void __launch_bounds__(256) bn_apply128_v4_kernel(const float* __restrict__ x, float* __restrict__ y,
                                                             int rows,
                                                             const float* __restrict__ gam, const float* __restrict__ bet,
                                                             const float* __restrict__ sums, const float* __restrict__ sqs) {
    size_t total = (size_t)rows * 32;   // float4 groups
    float invn = 1.f / (float)rows;
    for (size_t idx = (size_t)blockIdx.x * 256 + threadIdx.x; idx < total; idx += (size_t)gridDim.x * 256) {
        int c4 = (int)(idx & 31);
        float4 v = ((const float4*)x)[idx];
        float4 sm = ((const float4*)sums)[c4];
        float4 sq = ((const float4*)sqs)[c4];
        float4 gm = ((const float4*)gam)[c4];
        float4 bt = ((const float4*)bet)[c4];
        float mu0 = sm.x * invn, mu1 = sm.y * invn, mu2 = sm.z * invn, mu3 = sm.w * invn;
        float s0 = gm.x * rsqrtf(fmaf(-mu0, mu0, sq.x * invn) + EPSV);
        float s1 = gm.y * rsqrtf(fmaf(-mu1, mu1, sq.y * invn) + EPSV);
        float s2 = gm.z * rsqrtf(fmaf(-mu2, mu2, sq.z * invn) + EPSV);
        float s3 = gm.w * rsqrtf(fmaf(-mu3, mu3, sq.w * invn) + EPSV);
        float4 o;
        o.x = fmaxf(fmaf(v.x - mu0, s0, bt.x), 0.f);
        o.y = fmaxf(fmaf(v.y - mu1, s1, bt.y), 0.f);
        o.z = fmaxf(fmaf(v.z - mu2, s2, bt.z), 0.f);
        o.w = fmaxf(fmaf(v.w - mu3, s3, bt.w), 0.f);
        ((float4*)y)[idx] = o;
    }
}

// ---------------------------------------------------------------- launch
extern "C" void kernel_launch(void* const* d_in, const int* in_sizes, int n_in,
                              void* d_out, int out_size) {
    const float* feats = (const float*)d_in[0];
    const float* W1    = (const float*)d_in[1];
    const float* g1    = (const float*)d_in[3];
    const float* be1   = (const float*)d_in[4];
    const float* W2    = (const float*)d_in[5];
    const float* g2    = (const float*)d_in[7];
    const float* be2   = (const float*)d_in[8];
    const float* W3    = (const float*)d_in[9];
    const float* g3    = (const float*)d_in[11];
    const float* be3   = (const float*)d_in[12];
    const int* km_in   = (const int*)d_in[13];
    const int* km_out  = (const int*)d_in[14];
    const int* seg     = (const int*)d_in[15];
    const int* km2_in  = (const int*)d_in[16];
    const int* km2_out = (const int*)d_in[17];

    int N  = in_sizes[0];
    int M  = in_sizes[13] / 27;
    int M2 = in_sizes[16] / 27;
    int NP = out_size / 128;

    float *x1, *x2, *xp, *y3, *stats; int *nbr, *nbr2;
    cudaGetSymbolAddress((void**)&x1, g_x1);
    cudaGetSymbolAddress((void**)&x2, g_x2);
    cudaGetSymbolAddress((void**)&xp, g_xp);
    cudaGetSymbolAddress((void**)&y3, g_y3);
    cudaGetSymbolAddress((void**)&nbr, g_nbr);
    cudaGetSymbolAddress((void**)&nbr2, g_nbr2);
    cudaGetSymbolAddress((void**)&stats, g_stats);

    constexpr int SM2 = (64 * 128 + 64 * 64) * 8 + 192 * 4;             // 99072 (R8 config)
    constexpr int SM3 = 64 * 64 * 8 + 64 * 128 * 4 + 2 * 128 * 4;       // 66560 (Xd dup + plain W)
    cudaFuncSetAttribute((const void*)conv2_scatter_kernel,
                         cudaFuncAttributeMaxDynamicSharedMemorySize, SM2);
    cudaFuncSetAttribute((const void*)conv3_kernel,
                         cudaFuncAttributeMaxDynamicSharedMemorySize, SM3);

    int initThreads = (N + 1) * 64;
    if (27 * N > initThreads) initThreads = 27 * N;

    // (1) init: stats, sentinel tables, zero xp & x2
    initbig_kernel<<<(initThreads + 255) / 256, 256>>>(nbr, nbr2, xp, x2, stats, N, NP);
    // (2) neighbor table for layer 1 dense gather
    build_nbr_kernel<<<(27 * M + 255) / 256, 256>>>(km_in, km_out, nbr, M, N);
    // (3) conv1 + fused stats1
    conv1_kernel<<<(N + 63) / 64, 256>>>(feats, W1, x1, nbr, N, stats);
    // (4) conv2 scatter, 256-pair blocks, 2 CTAs/SM     <-- ncu capture target
    {
        dim3 grid((M + 255) / 256, 27);
        conv2_scatter_kernel<<<grid, 256, SM2>>>(
            x1, W2, x2, km_in, km_out, M, N,
            stats + 0, stats + 128, g1, be1, 1.f / (float)N);
    }
    // (5) neighbor table for layer 3
    build_nbr_kernel<<<(27 * M2 + 255) / 256, 256>>>(km2_in, km2_out, nbr2, M2, NP);
    // (6) BN2 stats
    bn_reduce_kernel<64><<<592, 256>>>(x2, N, stats + 256, stats + 384);
    // (7) BN2+ReLU fused with maxpool
    bn_apply_pool_kernel<<<1184, 256>>>(x2, seg, xp, N, g2, be2, stats + 256, stats + 384);
    // (8) conv3 dense, 3 CTAs/SM, transposed duplication (Xd/u64, W col-pairs) + fused stats3
    conv3_kernel<<<(NP + 63) / 64, 256, SM3>>>(
        xp, W3, y3, nbr2, NP, stats + 512, stats + 640);
    // (9) BN3+ReLU -> output (float4 vectorized)
    bn_apply128_v4_kernel<<<1184, 256>>>(y3, (float*)d_out, NP, g3, be3, stats + 512, stats + 640);
}

// round 15
// speedup vs baseline: 1.4985x; 1.4629x over previous
#include <cuda_runtime.h>
#include <cstdint>

#define EPSV 1e-5f
#define N_MAX   163904      // >= N+1 rows (N = 160000)
#define NP_MAX  65792       // >= NPOOL+1 rows

// -------- persistent scratch (no allocs allowed) --------
__device__ float g_x1[(size_t)N_MAX * 64];
__device__ float g_x2[(size_t)N_MAX * 64];
__device__ float g_xp[(size_t)NP_MAX * 64];
__device__ float g_y3[(size_t)NP_MAX * 128];
__device__ int   g_nbr [(size_t)N_MAX * 27];
__device__ int   g_nbr2[(size_t)NP_MAX * 27];
__device__ float g_stats[768];

typedef unsigned long long u64t;

__device__ __forceinline__ u64t pack2(float a, float b) {
    u64t r; unsigned x = __float_as_uint(a), y = __float_as_uint(b);
    asm("mov.b64 %0, {%1, %2};" : "=l"(r) : "r"(x), "r"(y));
    return r;
}
__device__ __forceinline__ void fma2(u64t& d, u64t a, u64t b) {
    asm("fma.rn.f32x2 %0, %1, %2, %0;" : "+l"(d) : "l"(a), "l"(b));
}
__device__ __forceinline__ float2 unpack2(u64t v) {
    unsigned lo, hi; asm("mov.b64 {%0, %1}, %2;" : "=r"(lo), "=r"(hi) : "l"(v));
    return make_float2(__uint_as_float(lo), __uint_as_float(hi));
}
__device__ __forceinline__ void redadd4(float* p, float4 v) {
    asm volatile("red.global.add.v4.f32 [%0], {%1,%2,%3,%4};"
                 :: "l"(p), "f"(v.x), "f"(v.y), "f"(v.z), "f"(v.w) : "memory");
}

// ---------------------------------------------------------------- init (stats, sentinels, zero x2/xp)
__global__ void initbig_kernel(int* __restrict__ nbr, int* __restrict__ nbr2,
                               float* __restrict__ xp, float* __restrict__ x2,
                               float* __restrict__ stats, int N, int NP) {
    int i = blockIdx.x * blockDim.x + threadIdx.x;
    if (i < 768) stats[i] = 0.f;
    if (i < 27 * N) nbr[i] = N;
    if (i < 27 * NP) nbr2[i] = NP;
    if (i < (NP + 1) * 64) xp[i] = 0.f;
    if (i < (N + 1) * 64) x2[i] = 0.f;
}
__global__ void build_nbr_kernel(const int* __restrict__ km_in, const int* __restrict__ km_out,
                                 int* __restrict__ nbr, int M, int Nr) {
    int idx = blockIdx.x * blockDim.x + threadIdx.x;
    if (idx >= 27 * M) return;
    int i = km_in[idx];
    if (i < Nr) {
        int k = idx / M;
        nbr[k * Nr + km_out[idx]] = i;
    }
}

// ---------------------------------------------------------------- conv1: 1 -> 64 channels, fused stats
__global__ void __launch_bounds__(256) conv1_kernel(const float* __restrict__ feats,
                                                    const float* __restrict__ W1,
                                                    float* __restrict__ out,
                                                    const int* __restrict__ nbr, int Nr,
                                                    float* __restrict__ stats) {
    __shared__ float fs[27 * 64];
    __shared__ float ws[27 * 64];
    __shared__ float sh[512];
    int t = threadIdx.x;
    int r0 = blockIdx.x * 64;
    for (int i = t; i < 27 * 64; i += 256) ws[i] = W1[i];
    for (int i = t; i < 27 * 64; i += 256) {
        int k = i >> 6, rr = i & 63, r = r0 + rr;
        float v = 0.f;
        if (r < Nr) {
            int g = nbr[k * Nr + r];
            if (g < Nr) v = feats[g];
        }
        fs[i] = v;
    }
    __syncthreads();
    int c = t & 63, rg = t >> 6;
    float s = 0.f, q = 0.f;
    #pragma unroll
    for (int ri = 0; ri < 16; ri++) {
        int rr = rg * 16 + ri, r = r0 + rr;
        if (r < Nr) {
            float acc = 0.f;
            #pragma unroll
            for (int k = 0; k < 27; k++) acc += fs[k * 64 + rr] * ws[k * 64 + c];
            out[(size_t)r * 64 + c] = acc;
            s += acc; q = fmaf(acc, acc, q);
        }
    }
    sh[t] = s; sh[256 + t] = q;
    __syncthreads();
    if (rg == 0) {
        #pragma unroll
        for (int g = 1; g < 4; g++) { s += sh[g * 64 + c]; q += sh[256 + g * 64 + c]; }
        atomicAdd(&stats[c], s);
        atomicAdd(&stats[128 + c], q);
    }
}

// ---------------------------------------------------------------- conv2: valid-pair scatter GEMM (256 pairs/block, 2 CTAs/SM — R8 config)
__global__ void __launch_bounds__(256, 2) conv2_scatter_kernel(
    const float* __restrict__ x1, const float* __restrict__ W2,
    float* __restrict__ x2,
    const int* __restrict__ km_in, const int* __restrict__ km_out,
    int M, int Nf,
    const float* __restrict__ sums, const float* __restrict__ sqs,
    const float* __restrict__ gam, const float* __restrict__ bet, float invn)
{
    const int k = blockIdx.y;
    const int p0 = blockIdx.x * 256;
    if (__ldg(km_in + (size_t)k * M + p0) >= Nf) return;   // front-packed: all-sentinel chunk

    extern __shared__ char smraw[];
    u64t* Xs = (u64t*)smraw;               // [64][128] row-pairs
    u64t* Wd = Xs + 64 * 128;              // [64][64]  duplicated weights
    float* bnc = (float*)(Wd + 64 * 64);   // mu[64], scl[64], be[64]

    const int t = threadIdx.x;
    const int tx = t & 15, ty = t >> 4;

    if (t < 64) {
        float mu = sums[t] * invn;
        float var = fmaf(-mu, mu, sqs[t] * invn);
        bnc[t] = mu;
        bnc[64 + t] = gam[t] * rsqrtf(var + EPSV);
        bnc[128 + t] = bet[t];
    }
    __syncthreads();

    // ---- gather 2 pair-rows per thread, 32 channels per half
    {
        const int grp = t & 127;
        const int j0 = (t >> 7) * 32;
        const int ra = p0 + 2 * grp, rb = ra + 1;
        int ga = (ra < M) ? __ldg(km_in + (size_t)k * M + ra) : Nf;
        int gb = (rb < M) ? __ldg(km_in + (size_t)k * M + rb) : Nf;
        const bool va = ga < Nf, vb = gb < Nf;
        const float4* pa = (const float4*)(x1 + (size_t)ga * 64) + (j0 >> 2);
        const float4* pb = (const float4*)(x1 + (size_t)gb * 64) + (j0 >> 2);
        #pragma unroll
        for (int q = 0; q < 8; q++) {
            float4 A = make_float4(0.f, 0.f, 0.f, 0.f), B = A;
            float4 mu = ((const float4*)bnc)[(j0 >> 2) + q];
            float4 sc = ((const float4*)(bnc + 64))[(j0 >> 2) + q];
            float4 be = ((const float4*)(bnc + 128))[(j0 >> 2) + q];
            if (va) {
                float4 v = pa[q];
                A.x = fmaxf(fmaf(v.x - mu.x, sc.x, be.x), 0.f);
                A.y = fmaxf(fmaf(v.y - mu.y, sc.y, be.y), 0.f);
                A.z = fmaxf(fmaf(v.z - mu.z, sc.z, be.z), 0.f);
                A.w = fmaxf(fmaf(v.w - mu.w, sc.w, be.w), 0.f);
            }
            if (vb) {
                float4 v = pb[q];
                B.x = fmaxf(fmaf(v.x - mu.x, sc.x, be.x), 0.f);
                B.y = fmaxf(fmaf(v.y - mu.y, sc.y, be.y), 0.f);
                B.z = fmaxf(fmaf(v.z - mu.z, sc.z, be.z), 0.f);
                B.w = fmaxf(fmaf(v.w - mu.w, sc.w, be.w), 0.f);
            }
            int j = j0 + 4 * q;
            Xs[(j + 0) * 128 + grp] = pack2(A.x, B.x);
            Xs[(j + 1) * 128 + grp] = pack2(A.y, B.y);
            Xs[(j + 2) * 128 + grp] = pack2(A.z, B.z);
            Xs[(j + 3) * 128 + grp] = pack2(A.w, B.w);
        }
        // weights, duplicated
        const float4* wk = (const float4*)(W2 + (size_t)k * 4096);
        #pragma unroll
        for (int i = 0; i < 4; i++) {
            float4 wv = wk[t + i * 256];
            int fi = (t + i * 256) * 4;
            Wd[fi + 0] = pack2(wv.x, wv.x);
            Wd[fi + 1] = pack2(wv.y, wv.y);
            Wd[fi + 2] = pack2(wv.z, wv.z);
            Wd[fi + 3] = pack2(wv.w, wv.w);
        }
    }
    __syncthreads();

    // ---- compute: 64 channels x (8 row-pairs x 4 cols)
    u64t acc[8][4];
    #pragma unroll
    for (int i = 0; i < 8; i++)
        #pragma unroll
        for (int c = 0; c < 4; c++) acc[i][c] = 0ULL;

    #pragma unroll 4
    for (int j = 0; j < 64; j++) {
        const u64t* ap = Xs + j * 128 + ty * 8;
        const u64t* bp = Wd + j * 64 + tx * 4;
        u64t a0 = ap[0], a1 = ap[1], a2 = ap[2], a3 = ap[3];
        u64t a4 = ap[4], a5 = ap[5], a6 = ap[6], a7 = ap[7];
        u64t b0 = bp[0], b1 = bp[1], b2 = bp[2], b3 = bp[3];
        fma2(acc[0][0], a0, b0); fma2(acc[0][1], a0, b1); fma2(acc[0][2], a0, b2); fma2(acc[0][3], a0, b3);
        fma2(acc[1][0], a1, b0); fma2(acc[1][1], a1, b1); fma2(acc[1][2], a1, b2); fma2(acc[1][3], a1, b3);
        fma2(acc[2][0], a2, b0); fma2(acc[2][1], a2, b1); fma2(acc[2][2], a2, b2); fma2(acc[2][3], a2, b3);
        fma2(acc[3][0], a3, b0); fma2(acc[3][1], a3, b1); fma2(acc[3][2], a3, b2); fma2(acc[3][3], a3, b3);
        fma2(acc[4][0], a4, b0); fma2(acc[4][1], a4, b1); fma2(acc[4][2], a4, b2); fma2(acc[4][3], a4, b3);
        fma2(acc[5][0], a5, b0); fma2(acc[5][1], a5, b1); fma2(acc[5][2], a5, b2); fma2(acc[5][3], a5, b3);
        fma2(acc[6][0], a6, b0); fma2(acc[6][1], a6, b1); fma2(acc[6][2], a6, b2); fma2(acc[6][3], a6, b3);
        fma2(acc[7][0], a7, b0); fma2(acc[7][1], a7, b1); fma2(acc[7][2], a7, b2); fma2(acc[7][3], a7, b3);
    }

    // ---- scatter epilogue: v4 vector reds, skip sentinels
    #pragma unroll
    for (int i = 0; i < 8; i++) {
        int pr = p0 + ty * 16 + 2 * i;
        int oa = (pr < M) ? __ldg(km_out + (size_t)k * M + pr) : Nf;
        int ob = (pr + 1 < M) ? __ldg(km_out + (size_t)k * M + pr + 1) : Nf;
        float2 e0 = unpack2(acc[i][0]), e1 = unpack2(acc[i][1]);
        float2 e2 = unpack2(acc[i][2]), e3 = unpack2(acc[i][3]);
        if (oa < Nf)
            redadd4(x2 + (size_t)oa * 64 + tx * 4, make_float4(e0.x, e1.x, e2.x, e3.x));
        if (ob < Nf)
            redadd4(x2 + (size_t)ob * 64 + tx * 4, make_float4(e0.y, e1.y, e2.y, e3.y));
    }
}

// ---------------------------------------------------------------- conv3: dense gather 64 rows x 128 cols, 3 CTAs/SM + X-only prefetch (R12)
__global__ void __launch_bounds__(256, 3) conv3_kernel(
    const float* __restrict__ x, const float* __restrict__ W,
    float* __restrict__ out, const int* __restrict__ nbr, int Nr,
    float* __restrict__ oS, float* __restrict__ oQ)
{
    extern __shared__ char smraw[];
    u64t* Xs = (u64t*)smraw;              // [64 j][32 row-pairs]  (16 KB)
    float* Ws = (float*)(Xs + 64 * 32);   // [64 j][128 c] plain floats (32 KB)
    float* redS = Ws + 64 * 128;
    float* redQ = redS + 128;

    const int t = threadIdx.x;
    const int tx = t & 31, ty = t >> 5;   // warp-uniform ty
    const int r0 = blockIdx.x * 64;
    const int grp = t & 31;
    const int j0 = (t >> 5) * 8;

    if (t < 128) { redS[t] = 0.f; redQ[t] = 0.f; }

    u64t acc[4][4];
    #pragma unroll
    for (int i = 0; i < 4; i++)
        #pragma unroll
        for (int c = 0; c < 4; c++) acc[i][c] = 0ULL;

    const int ra = r0 + 2 * grp, rb = ra + 1;

    float4 xpre[4];   // 2 gathered rows x 8 floats (16 regs)

    auto ldg_x = [&](int k) {
        int ga = (ra < Nr) ? __ldg(nbr + (size_t)k * Nr + ra) : Nr;
        int gb = (rb < Nr) ? __ldg(nbr + (size_t)k * Nr + rb) : Nr;
        const float4* pa = (const float4*)(x + (size_t)ga * 64) + (j0 >> 2);
        const float4* pb = (const float4*)(x + (size_t)gb * 64) + (j0 >> 2);
        xpre[0] = pa[0]; xpre[1] = pa[1];
        xpre[2] = pb[0]; xpre[3] = pb[1];
    };

    ldg_x(0);   // prologue

    for (int k = 0; k < 27; k++) {
        __syncthreads();    // previous compute done; Xs/Ws free
        // STS prefetched X (pack row pairs)
        #pragma unroll
        for (int q = 0; q < 2; q++) {
            float4 va = xpre[q], vb = xpre[2 + q];
            int j = j0 + 4 * q;
            Xs[(j + 0) * 32 + grp] = pack2(va.x, vb.x);
            Xs[(j + 1) * 32 + grp] = pack2(va.y, vb.y);
            Xs[(j + 2) * 32 + grp] = pack2(va.z, vb.z);
            Xs[(j + 3) * 32 + grp] = pack2(va.w, vb.w);
        }
        // W tile: LDG->STS (independent loads; single exposed L2 latency)
        const float4* wk = (const float4*)(W + (size_t)k * 8192);
        #pragma unroll
        for (int i = 0; i < 8; i++)
            ((float4*)Ws)[t + i * 256] = wk[t + i * 256];
        __syncthreads();

        if (k < 26) ldg_x(k + 1);   // X gather chain for k+1 in flight under compute(k)

        #pragma unroll 4
        for (int j = 0; j < 64; j++) {
            const u64t* ap = Xs + j * 32 + ty * 4;
            float4 bw = ((const float4*)(Ws + j * 128))[tx];
            u64t a0 = ap[0], a1 = ap[1], a2 = ap[2], a3 = ap[3];
            u64t b0 = pack2(bw.x, bw.x), b1 = pack2(bw.y, bw.y);
            u64t b2 = pack2(bw.z, bw.z), b3 = pack2(bw.w, bw.w);
            fma2(acc[0][0], a0, b0); fma2(acc[0][1], a0, b1); fma2(acc[0][2], a0, b2); fma2(acc[0][3], a0, b3);
            fma2(acc[1][0], a1, b0); fma2(acc[1][1], a1, b1); fma2(acc[1][2], a1, b2); fma2(acc[1][3], a1, b3);
            fma2(acc[2][0], a2, b0); fma2(acc[2][1], a2, b1); fma2(acc[2][2], a2, b2); fma2(acc[2][3], a2, b3);
            fma2(acc[3][0], a3, b0); fma2(acc[3][1], a3, b1); fma2(acc[3][2], a3, b2); fma2(acc[3][3], a3, b3);
        }
    }

    // ---- epilogue: store + fused BN stats partials
    float scol[4] = {0.f, 0.f, 0.f, 0.f}, qcol[4] = {0.f, 0.f, 0.f, 0.f};
    #pragma unroll
    for (int i = 0; i < 4; i++) {
        float2 e0 = unpack2(acc[i][0]), e1 = unpack2(acc[i][1]);
        float2 e2 = unpack2(acc[i][2]), e3 = unpack2(acc[i][3]);
        int re = r0 + ty * 8 + 2 * i;
        if (re < Nr) {
            *(float4*)(out + (size_t)re * 128 + tx * 4) = make_float4(e0.x, e1.x, e2.x, e3.x);
            scol[0] += e0.x; qcol[0] = fmaf(e0.x, e0.x, qcol[0]);
            scol[1] += e1.x; qcol[1] = fmaf(e1.x, e1.x, qcol[1]);
            scol[2] += e2.x; qcol[2] = fmaf(e2.x, e2.x, qcol[2]);
            scol[3] += e3.x; qcol[3] = fmaf(e3.x, e3.x, qcol[3]);
        }
        if (re + 1 < Nr) {
            *(float4*)(out + (size_t)(re + 1) * 128 + tx * 4) = make_float4(e0.y, e1.y, e2.y, e3.y);
            scol[0] += e0.y; qcol[0] = fmaf(e0.y, e0.y, qcol[0]);
            scol[1] += e1.y; qcol[1] = fmaf(e1.y, e1.y, qcol[1]);
            scol[2] += e2.y; qcol[2] = fmaf(e2.y, e2.y, qcol[2]);
            scol[3] += e3.y; qcol[3] = fmaf(e3.y, e3.y, qcol[3]);
        }
    }
    __syncthreads();
    #pragma unroll
    for (int c = 0; c < 4; c++) {
        atomicAdd(&redS[tx * 4 + c], scol[c]);
        atomicAdd(&redQ[tx * 4 + c], qcol[c]);
    }
    __syncthreads();
    if (t < 128) {
        atomicAdd(&oS[t], redS[t]);
        atomicAdd(&oQ[t], redQ[t]);
    }
}

// ---------------------------------------------------------------- BN reduce / apply / pool
template<int C>
__global__ void __launch_bounds__(256) bn_reduce_kernel(const float* __restrict__ x, int rows,
                                                        float* __restrict__ sumo, float* __restrict__ sqo) {
    constexpr int G = 256 / C;
    int t = threadIdx.x, c = t & (C - 1), rg = t / C;
    float s = 0.f, q = 0.f;
    for (int r = blockIdx.x * G + rg; r < rows; r += gridDim.x * G) {
        float v = x[(size_t)r * C + c];
        s += v; q = fmaf(v, v, q);
    }
    __shared__ float sh[512];
    sh[t] = s; sh[256 + t] = q;
    __syncthreads();
    if (rg == 0) {
        #pragma unroll
        for (int g = 1; g < G; g++) { s += sh[g * C + c]; q += sh[256 + g * C + c]; }
        atomicAdd(&sumo[c], s);
        atomicAdd(&sqo[c], q);
    }
}

__global__ void __launch_bounds__(256) bn_apply_pool_kernel(const float* __restrict__ x,
                                                            const int* __restrict__ seg,
                                                            float* __restrict__ xp, int rows,
                                                            const float* __restrict__ gam, const float* __restrict__ bet,
                                                            const float* __restrict__ sums, const float* __restrict__ sqs) {
    size_t total = (size_t)rows * 64;
    float invn = 1.f / (float)rows;
    for (size_t idx = (size_t)blockIdx.x * 256 + threadIdx.x; idx < total; idx += (size_t)gridDim.x * 256) {
        int c = (int)(idx & 63);
        int r = (int)(idx >> 6);
        float mu = sums[c] * invn;
        float var = fmaf(-mu, mu, sqs[c] * invn);
        float scl = gam[c] * rsqrtf(var + EPSV);
        float v = fmaxf(fmaf(x[idx] - mu, scl, bet[c]), 0.f);
        atomicMax((unsigned int*)&xp[(size_t)seg[r] * 64 + c], __float_as_uint(v));
    }
}

// final BN apply, float4-vectorized (C=128)
__global__ void __launch_bounds__(256) bn_apply128_v4_kernel(const float* __restrict__ x, float* __restrict__ y,
                                                             int rows,
                                                             const float* __restrict__ gam, const float* __restrict__ bet,
                                                             const float* __restrict__ sums, const float* __restrict__ sqs) {
    size_t total = (size_t)rows * 32;   // float4 groups
    float invn = 1.f / (float)rows;
    for (size_t idx = (size_t)blockIdx.x * 256 + threadIdx.x; idx < total; idx += (size_t)gridDim.x * 256) {
        int c4 = (int)(idx & 31);
        float4 v = ((const float4*)x)[idx];
        float4 sm = ((const float4*)sums)[c4];
        float4 sq = ((const float4*)sqs)[c4];
        float4 gm = ((const float4*)gam)[c4];
        float4 bt = ((const float4*)bet)[c4];
        float mu0 = sm.x * invn, mu1 = sm.y * invn, mu2 = sm.z * invn, mu3 = sm.w * invn;
        float s0 = gm.x * rsqrtf(fmaf(-mu0, mu0, sq.x * invn) + EPSV);
        float s1 = gm.y * rsqrtf(fmaf(-mu1, mu1, sq.y * invn) + EPSV);
        float s2 = gm.z * rsqrtf(fmaf(-mu2, mu2, sq.z * invn) + EPSV);
        float s3 = gm.w * rsqrtf(fmaf(-mu3, mu3, sq.w * invn) + EPSV);
        float4 o;
        o.x = fmaxf(fmaf(v.x - mu0, s0, bt.x), 0.f);
        o.y = fmaxf(fmaf(v.y - mu1, s1, bt.y), 0.f);
        o.z = fmaxf(fmaf(v.z - mu2, s2, bt.z), 0.f);
        o.w = fmaxf(fmaf(v.w - mu3, s3, bt.w), 0.f);
        ((float4*)y)[idx] = o;
    }
}

// ---------------------------------------------------------------- launch
extern "C" void kernel_launch(void* const* d_in, const int* in_sizes, int n_in,
                              void* d_out, int out_size) {
    const float* feats = (const float*)d_in[0];
    const float* W1    = (const float*)d_in[1];
    const float* g1    = (const float*)d_in[3];
    const float* be1   = (const float*)d_in[4];
    const float* W2    = (const float*)d_in[5];
    const float* g2    = (const float*)d_in[7];
    const float* be2   = (const float*)d_in[8];
    const float* W3    = (const float*)d_in[9];
    const float* g3    = (const float*)d_in[11];
    const float* be3   = (const float*)d_in[12];
    const int* km_in   = (const int*)d_in[13];
    const int* km_out  = (const int*)d_in[14];
    const int* seg     = (const int*)d_in[15];
    const int* km2_in  = (const int*)d_in[16];
    const int* km2_out = (const int*)d_in[17];

    int N  = in_sizes[0];
    int M  = in_sizes[13] / 27;
    int M2 = in_sizes[16] / 27;
    int NP = out_size / 128;

    float *x1, *x2, *xp, *y3, *stats; int *nbr, *nbr2;
    cudaGetSymbolAddress((void**)&x1, g_x1);
    cudaGetSymbolAddress((void**)&x2, g_x2);
    cudaGetSymbolAddress((void**)&xp, g_xp);
    cudaGetSymbolAddress((void**)&y3, g_y3);
    cudaGetSymbolAddress((void**)&nbr, g_nbr);
    cudaGetSymbolAddress((void**)&nbr2, g_nbr2);
    cudaGetSymbolAddress((void**)&stats, g_stats);

    constexpr int SM2 = (64 * 128 + 64 * 64) * 8 + 192 * 4;             // 99072 (R8 config)
    constexpr int SM3 = 64 * 32 * 8 + 64 * 128 * 4 + 2 * 128 * 4;       // 50176 (R12 config)
    cudaFuncSetAttribute((const void*)conv2_scatter_kernel,
                         cudaFuncAttributeMaxDynamicSharedMemorySize, SM2);
    cudaFuncSetAttribute((const void*)conv3_kernel,
                         cudaFuncAttributeMaxDynamicSharedMemorySize, SM3);

    int initThreads = (N + 1) * 64;
    if (27 * N > initThreads) initThreads = 27 * N;

    // (1) init: stats, sentinel tables, zero xp & x2
    initbig_kernel<<<(initThreads + 255) / 256, 256>>>(nbr, nbr2, xp, x2, stats, N, NP);
    // (2) neighbor table for layer 1 dense gather
    build_nbr_kernel<<<(27 * M + 255) / 256, 256>>>(km_in, km_out, nbr, M, N);
    // (3) conv1 + fused stats1
    conv1_kernel<<<(N + 63) / 64, 256>>>(feats, W1, x1, nbr, N, stats);
    // (4) conv2 scatter, 256-pair blocks, 2 CTAs/SM     <-- ncu capture target
    {
        dim3 grid((M + 255) / 256, 27);
        conv2_scatter_kernel<<<grid, 256, SM2>>>(
            x1, W2, x2, km_in, km_out, M, N,
            stats + 0, stats + 128, g1, be1, 1.f / (float)N);
    }
    // (5) neighbor table for layer 3
    build_nbr_kernel<<<(27 * M2 + 255) / 256, 256>>>(km2_in, km2_out, nbr2, M2, NP);
    // (6) BN2 stats
    bn_reduce_kernel<64><<<1184, 256>>>(x2, N, stats + 256, stats + 384);
    // (7) BN2+ReLU fused with maxpool
    bn_apply_pool_kernel<<<1184, 256>>>(x2, seg, xp, N, g2, be2, stats + 256, stats + 384);
    // (8) conv3 dense (R12 proven config) + fused stats3
    conv3_kernel<<<(NP + 63) / 64, 256, SM3>>>(
        xp, W3, y3, nbr2, NP, stats + 512, stats + 640);
    // (9) BN3+ReLU -> output (float4 vectorized)
    bn_apply128_v4_kernel<<<1184, 256>>>(y3, (float*)d_out, NP, g3, be3, stats + 512, stats + 640);
}

// round 16
// speedup vs baseline: 1.5362x; 1.0252x over previous
#include <cuda_runtime.h>
#include <cstdint>

#define EPSV 1e-5f
#define N_MAX   163904      // >= N+1 rows (N = 160000)
#define NP_MAX  65792       // >= NPOOL+1 rows

// -------- persistent scratch (no allocs allowed) --------
__device__ float g_x1[(size_t)N_MAX * 64];
__device__ float g_x2[(size_t)N_MAX * 64];
__device__ float g_xp[(size_t)NP_MAX * 64];
__device__ float g_y3[(size_t)NP_MAX * 128];
__device__ int   g_nbr [(size_t)N_MAX * 27];
__device__ int   g_nbr2[(size_t)NP_MAX * 27];
__device__ float g_stats[768];

typedef unsigned long long u64t;

__device__ __forceinline__ u64t pack2(float a, float b) {
    u64t r; unsigned x = __float_as_uint(a), y = __float_as_uint(b);
    asm("mov.b64 %0, {%1, %2};" : "=l"(r) : "r"(x), "r"(y));
    return r;
}
__device__ __forceinline__ void fma2(u64t& d, u64t a, u64t b) {
    asm("fma.rn.f32x2 %0, %1, %2, %0;" : "+l"(d) : "l"(a), "l"(b));
}
__device__ __forceinline__ float2 unpack2(u64t v) {
    unsigned lo, hi; asm("mov.b64 {%0, %1}, %2;" : "=r"(lo), "=r"(hi) : "l"(v));
    return make_float2(__uint_as_float(lo), __uint_as_float(hi));
}
__device__ __forceinline__ void redadd4(float* p, float4 v) {
    asm volatile("red.global.add.v4.f32 [%0], {%1,%2,%3,%4};"
                 :: "l"(p), "f"(v.x), "f"(v.y), "f"(v.z), "f"(v.w) : "memory");
}

// ---------------------------------------------------------------- init (stats, sentinels, zero x2/xp)
__global__ void initbig_kernel(int* __restrict__ nbr, int* __restrict__ nbr2,
                               float* __restrict__ xp, float* __restrict__ x2,
                               float* __restrict__ stats, int N, int NP) {
    int i = blockIdx.x * blockDim.x + threadIdx.x;
    if (i < 768) stats[i] = 0.f;
    if (i < 27 * N) nbr[i] = N;
    if (i < 27 * NP) nbr2[i] = NP;
    if (i < (NP + 1) * 64) xp[i] = 0.f;
    if (i < (N + 1) * 64) x2[i] = 0.f;
}
__global__ void build_nbr_kernel(const int* __restrict__ km_in, const int* __restrict__ km_out,
                                 int* __restrict__ nbr, int M, int Nr) {
    int idx = blockIdx.x * blockDim.x + threadIdx.x;
    if (idx >= 27 * M) return;
    int i = km_in[idx];
    if (i < Nr) {
        int k = idx / M;
        nbr[k * Nr + km_out[idx]] = i;
    }
}

// ---------------------------------------------------------------- conv1: 1 -> 64 channels, fused stats
__global__ void __launch_bounds__(256) conv1_kernel(const float* __restrict__ feats,
                                                    const float* __restrict__ W1,
                                                    float* __restrict__ out,
                                                    const int* __restrict__ nbr, int Nr,
                                                    float* __restrict__ stats) {
    __shared__ float fs[27 * 64];
    __shared__ float ws[27 * 64];
    __shared__ float sh[512];
    int t = threadIdx.x;
    int r0 = blockIdx.x * 64;
    for (int i = t; i < 27 * 64; i += 256) ws[i] = W1[i];
    for (int i = t; i < 27 * 64; i += 256) {
        int k = i >> 6, rr = i & 63, r = r0 + rr;
        float v = 0.f;
        if (r < Nr) {
            int g = nbr[k * Nr + r];
            if (g < Nr) v = feats[g];
        }
        fs[i] = v;
    }
    __syncthreads();
    int c = t & 63, rg = t >> 6;
    float s = 0.f, q = 0.f;
    #pragma unroll
    for (int ri = 0; ri < 16; ri++) {
        int rr = rg * 16 + ri, r = r0 + rr;
        if (r < Nr) {
            float acc = 0.f;
            #pragma unroll
            for (int k = 0; k < 27; k++) acc += fs[k * 64 + rr] * ws[k * 64 + c];
            out[(size_t)r * 64 + c] = acc;
            s += acc; q = fmaf(acc, acc, q);
        }
    }
    sh[t] = s; sh[256 + t] = q;
    __syncthreads();
    if (rg == 0) {
        #pragma unroll
        for (int g = 1; g < 4; g++) { s += sh[g * 64 + c]; q += sh[256 + g * 64 + c]; }
        atomicAdd(&stats[c], s);
        atomicAdd(&stats[128 + c], q);
    }
}

// ---------------------------------------------------------------- conv2: valid-pair scatter GEMM (256 pairs/block, 2 CTAs/SM)
// v2 gather: 8 lanes per gathered row (coalesced LDG, 4 wavefronts/instr) storing a
// TRANSPOSED bank-swizzled tile Xs[ch][pair] -- the (rowA,rowB) u64 operand is then
// just two adjacent floats, so no packing is needed anywhere.
__global__ void __launch_bounds__(256, 2) conv2_scatter_kernel(
    const float* __restrict__ x1, const float* __restrict__ W2,
    float* __restrict__ x2,
    const int* __restrict__ km_in, const int* __restrict__ km_out,
    int M, int Nf,
    const float* __restrict__ sums, const float* __restrict__ sqs,
    const float* __restrict__ gam, const float* __restrict__ bet, float invn)
{
    const int k = blockIdx.y;
    const int p0 = blockIdx.x * 256;
    if (__ldg(km_in + (size_t)k * M + p0) >= Nf) return;   // front-packed: all-sentinel chunk

    extern __shared__ char smraw[];
    u64t* Xs = (u64t*)smraw;               // viewed as float[64 ch][256 pairs] (64 KB)
    u64t* Wd = Xs + 64 * 128;              // [64][64] duplicated weights
    float* bnc = (float*)(Wd + 64 * 64);   // mu[64], scl[64], be[64]
    float* Xsf = (float*)Xs;

    const int t = threadIdx.x;
    const int tx = t & 15, ty = t >> 4;

    if (t < 64) {
        float mu = sums[t] * invn;
        float var = fmaf(-mu, mu, sqs[t] * invn);
        bnc[t] = mu;
        bnc[64 + t] = gam[t] * rsqrtf(var + EPSV);
        bnc[128 + t] = bet[t];
    }
    __syncthreads();

    // ---- gather v2: coalesced 8-lanes-per-row, transposed swizzled store
    {
        const int lrow = t & 7;           // lane within row: pieces lrow, lrow+8
        const int rgrp = (t >> 3) & 3;    // row within warp step (4 rows/warp)
        const int w = t >> 5;
        const uint32_t sw = (uint32_t)(lrow & 3) << 3;   // = ((c>>2)&3)<<3 for c = 4q..
        #pragma unroll
        for (int s = 0; s < 8; s++) {
            int p = s * 32 + w * 4 + rgrp;
            int gp = p0 + p;
            int g = (gp < M) ? __ldg(km_in + (size_t)k * M + gp) : Nf;
            const bool valid = g < Nf;
            const float4* src = (const float4*)(x1 + (size_t)g * 64);
            const int pp = p ^ (int)sw;
            #pragma unroll
            for (int h = 0; h < 2; h++) {
                int q = lrow + h * 8;
                float4 v = make_float4(0.f, 0.f, 0.f, 0.f);
                if (valid) {
                    float4 xv = src[q];
                    float4 mu = ((const float4*)bnc)[q];
                    float4 sc = ((const float4*)(bnc + 64))[q];
                    float4 be = ((const float4*)(bnc + 128))[q];
                    v.x = fmaxf(fmaf(xv.x - mu.x, sc.x, be.x), 0.f);
                    v.y = fmaxf(fmaf(xv.y - mu.y, sc.y, be.y), 0.f);
                    v.z = fmaxf(fmaf(xv.z - mu.z, sc.z, be.z), 0.f);
                    v.w = fmaxf(fmaf(xv.w - mu.w, sc.w, be.w), 0.f);
                }
                int c0 = 4 * q;
                Xsf[(c0 + 0) * 256 + pp] = v.x;
                Xsf[(c0 + 1) * 256 + pp] = v.y;
                Xsf[(c0 + 2) * 256 + pp] = v.z;
                Xsf[(c0 + 3) * 256 + pp] = v.w;
            }
        }
        // weights, duplicated (unchanged)
        const float4* wk = (const float4*)(W2 + (size_t)k * 4096);
        #pragma unroll
        for (int i = 0; i < 4; i++) {
            float4 wv = wk[t + i * 256];
            int fi = (t + i * 256) * 4;
            Wd[fi + 0] = pack2(wv.x, wv.x);
            Wd[fi + 1] = pack2(wv.y, wv.y);
            Wd[fi + 2] = pack2(wv.z, wv.z);
            Wd[fi + 3] = pack2(wv.w, wv.w);
        }
    }
    __syncthreads();

    // ---- compute: 64 channels x (8 row-pairs x 4 cols); a-reads deswizzled per j
    u64t acc[8][4];
    #pragma unroll
    for (int i = 0; i < 8; i++)
        #pragma unroll
        for (int c = 0; c < 4; c++) acc[i][c] = 0ULL;

    #pragma unroll 4
    for (int j = 0; j < 64; j++) {
        const uint32_t swj = (uint32_t)((j >> 2) & 3) << 3;
        const u64t* ap1 = (const u64t*)(Xsf + j * 256 + ((ty * 16) ^ swj));
        const u64t* ap2 = (const u64t*)(Xsf + j * 256 + ((ty * 16 + 8) ^ swj));
        const u64t* bp = Wd + j * 64 + tx * 4;
        u64t a0 = ap1[0], a1 = ap1[1], a2 = ap1[2], a3 = ap1[3];
        u64t a4 = ap2[0], a5 = ap2[1], a6 = ap2[2], a7 = ap2[3];
        u64t b0 = bp[0], b1 = bp[1], b2 = bp[2], b3 = bp[3];
        fma2(acc[0][0], a0, b0); fma2(acc[0][1], a0, b1); fma2(acc[0][2], a0, b2); fma2(acc[0][3], a0, b3);
        fma2(acc[1][0], a1, b0); fma2(acc[1][1], a1, b1); fma2(acc[1][2], a1, b2); fma2(acc[1][3], a1, b3);
        fma2(acc[2][0], a2, b0); fma2(acc[2][1], a2, b1); fma2(acc[2][2], a2, b2); fma2(acc[2][3], a2, b3);
        fma2(acc[3][0], a3, b0); fma2(acc[3][1], a3, b1); fma2(acc[3][2], a3, b2); fma2(acc[3][3], a3, b3);
        fma2(acc[4][0], a4, b0); fma2(acc[4][1], a4, b1); fma2(acc[4][2], a4, b2); fma2(acc[4][3], a4, b3);
        fma2(acc[5][0], a5, b0); fma2(acc[5][1], a5, b1); fma2(acc[5][2], a5, b2); fma2(acc[5][3], a5, b3);
        fma2(acc[6][0], a6, b0); fma2(acc[6][1], a6, b1); fma2(acc[6][2], a6, b2); fma2(acc[6][3], a6, b3);
        fma2(acc[7][0], a7, b0); fma2(acc[7][1], a7, b1); fma2(acc[7][2], a7, b2); fma2(acc[7][3], a7, b3);
    }

    // ---- scatter epilogue: v4 vector reds, skip sentinels (mapping unchanged)
    #pragma unroll
    for (int i = 0; i < 8; i++) {
        int pr = p0 + ty * 16 + 2 * i;
        int oa = (pr < M) ? __ldg(km_out + (size_t)k * M + pr) : Nf;
        int ob = (pr + 1 < M) ? __ldg(km_out + (size_t)k * M + pr + 1) : Nf;
        float2 e0 = unpack2(acc[i][0]), e1 = unpack2(acc[i][1]);
        float2 e2 = unpack2(acc[i][2]), e3 = unpack2(acc[i][3]);
        if (oa < Nf)
            redadd4(x2 + (size_t)oa * 64 + tx * 4, make_float4(e0.x, e1.x, e2.x, e3.x));
        if (ob < Nf)
            redadd4(x2 + (size_t)ob * 64 + tx * 4, make_float4(e0.y, e1.y, e2.y, e3.y));
    }
}

// ---------------------------------------------------------------- conv3: dense gather 64 rows x 128 cols, 3 CTAs/SM + X-only prefetch (R12)
__global__ void __launch_bounds__(256, 3) conv3_kernel(
    const float* __restrict__ x, const float* __restrict__ W,
    float* __restrict__ out, const int* __restrict__ nbr, int Nr,
    float* __restrict__ oS, float* __restrict__ oQ)
{
    extern __shared__ char smraw[];
    u64t* Xs = (u64t*)smraw;              // [64 j][32 row-pairs]  (16 KB)
    float* Ws = (float*)(Xs + 64 * 32);   // [64 j][128 c] plain floats (32 KB)
    float* redS = Ws + 64 * 128;
    float* redQ = redS + 128;

    const int t = threadIdx.x;
    const int tx = t & 31, ty = t >> 5;   // warp-uniform ty
    const int r0 = blockIdx.x * 64;
    const int grp = t & 31;
    const int j0 = (t >> 5) * 8;

    if (t < 128) { redS[t] = 0.f; redQ[t] = 0.f; }

    u64t acc[4][4];
    #pragma unroll
    for (int i = 0; i < 4; i++)
        #pragma unroll
        for (int c = 0; c < 4; c++) acc[i][c] = 0ULL;

    const int ra = r0 + 2 * grp, rb = ra + 1;

    float4 xpre[4];   // 2 gathered rows x 8 floats (16 regs)

    auto ldg_x = [&](int k) {
        int ga = (ra < Nr) ? __ldg(nbr + (size_t)k * Nr + ra) : Nr;
        int gb = (rb < Nr) ? __ldg(nbr + (size_t)k * Nr + rb) : Nr;
        const float4* pa = (const float4*)(x + (size_t)ga * 64) + (j0 >> 2);
        const float4* pb = (const float4*)(x + (size_t)gb * 64) + (j0 >> 2);
        xpre[0] = pa[0]; xpre[1] = pa[1];
        xpre[2] = pb[0]; xpre[3] = pb[1];
    };

    ldg_x(0);   // prologue

    for (int k = 0; k < 27; k++) {
        __syncthreads();    // previous compute done; Xs/Ws free
        #pragma unroll
        for (int q = 0; q < 2; q++) {
            float4 va = xpre[q], vb = xpre[2 + q];
            int j = j0 + 4 * q;
            Xs[(j + 0) * 32 + grp] = pack2(va.x, vb.x);
            Xs[(j + 1) * 32 + grp] = pack2(va.y, vb.y);
            Xs[(j + 2) * 32 + grp] = pack2(va.z, vb.z);
            Xs[(j + 3) * 32 + grp] = pack2(va.w, vb.w);
        }
        const float4* wk = (const float4*)(W + (size_t)k * 8192);
        #pragma unroll
        for (int i = 0; i < 8; i++)
            ((float4*)Ws)[t + i * 256] = wk[t + i * 256];
        __syncthreads();

        if (k < 26) ldg_x(k + 1);   // X gather chain for k+1 in flight under compute(k)

        #pragma unroll 4
        for (int j = 0; j < 64; j++) {
            const u64t* ap = Xs + j * 32 + ty * 4;
            float4 bw = ((const float4*)(Ws + j * 128))[tx];
            u64t a0 = ap[0], a1 = ap[1], a2 = ap[2], a3 = ap[3];
            u64t b0 = pack2(bw.x, bw.x), b1 = pack2(bw.y, bw.y);
            u64t b2 = pack2(bw.z, bw.z), b3 = pack2(bw.w, bw.w);
            fma2(acc[0][0], a0, b0); fma2(acc[0][1], a0, b1); fma2(acc[0][2], a0, b2); fma2(acc[0][3], a0, b3);
            fma2(acc[1][0], a1, b0); fma2(acc[1][1], a1, b1); fma2(acc[1][2], a1, b2); fma2(acc[1][3], a1, b3);
            fma2(acc[2][0], a2, b0); fma2(acc[2][1], a2, b1); fma2(acc[2][2], a2, b2); fma2(acc[2][3], a2, b3);
            fma2(acc[3][0], a3, b0); fma2(acc[3][1], a3, b1); fma2(acc[3][2], a3, b2); fma2(acc[3][3], a3, b3);
        }
    }

    // ---- epilogue: store + fused BN stats partials
    float scol[4] = {0.f, 0.f, 0.f, 0.f}, qcol[4] = {0.f, 0.f, 0.f, 0.f};
    #pragma unroll
    for (int i = 0; i < 4; i++) {
        float2 e0 = unpack2(acc[i][0]), e1 = unpack2(acc[i][1]);
        float2 e2 = unpack2(acc[i][2]), e3 = unpack2(acc[i][3]);
        int re = r0 + ty * 8 + 2 * i;
        if (re < Nr) {
            *(float4*)(out + (size_t)re * 128 + tx * 4) = make_float4(e0.x, e1.x, e2.x, e3.x);
            scol[0] += e0.x; qcol[0] = fmaf(e0.x, e0.x, qcol[0]);
            scol[1] += e1.x; qcol[1] = fmaf(e1.x, e1.x, qcol[1]);
            scol[2] += e2.x; qcol[2] = fmaf(e2.x, e2.x, qcol[2]);
            scol[3] += e3.x; qcol[3] = fmaf(e3.x, e3.x, qcol[3]);
        }
        if (re + 1 < Nr) {
            *(float4*)(out + (size_t)(re + 1) * 128 + tx * 4) = make_float4(e0.y, e1.y, e2.y, e3.y);
            scol[0] += e0.y; qcol[0] = fmaf(e0.y, e0.y, qcol[0]);
            scol[1] += e1.y; qcol[1] = fmaf(e1.y, e1.y, qcol[1]);
            scol[2] += e2.y; qcol[2] = fmaf(e2.y, e2.y, qcol[2]);
            scol[3] += e3.y; qcol[3] = fmaf(e3.y, e3.y, qcol[3]);
        }
    }
    __syncthreads();
    #pragma unroll
    for (int c = 0; c < 4; c++) {
        atomicAdd(&redS[tx * 4 + c], scol[c]);
        atomicAdd(&redQ[tx * 4 + c], qcol[c]);
    }
    __syncthreads();
    if (t < 128) {
        atomicAdd(&oS[t], redS[t]);
        atomicAdd(&oQ[t], redQ[t]);
    }
}

// ---------------------------------------------------------------- BN reduce / apply / pool
template<int C>
__global__ void __launch_bounds__(256) bn_reduce_kernel(const float* __restrict__ x, int rows,
                                                        float* __restrict__ sumo, float* __restrict__ sqo) {
    constexpr int G = 256 / C;
    int t = threadIdx.x, c = t & (C - 1), rg = t / C;
    float s = 0.f, q = 0.f;
    for (int r = blockIdx.x * G + rg; r < rows; r += gridDim.x * G) {
        float v = x[(size_t)r * C + c];
        s += v; q = fmaf(v, v, q);
    }
    __shared__ float sh[512];
    sh[t] = s; sh[256 + t] = q;
    __syncthreads();
    if (rg == 0) {
        #pragma unroll
        for (int g = 1; g < G; g++) { s += sh[g * C + c]; q += sh[256 + g * C + c]; }
        atomicAdd(&sumo[c], s);
        atomicAdd(&sqo[c], q);
    }
}

__global__ void __launch_bounds__(256) bn_apply_pool_kernel(const float* __restrict__ x,
                                                            const int* __restrict__ seg,
                                                            float* __restrict__ xp, int rows,
                                                            const float* __restrict__ gam, const float* __restrict__ bet,
                                                            const float* __restrict__ sums, const float* __restrict__ sqs) {
    size_t total = (size_t)rows * 64;
    float invn = 1.f / (float)rows;
    for (size_t idx = (size_t)blockIdx.x * 256 + threadIdx.x; idx < total; idx += (size_t)gridDim.x * 256) {
        int c = (int)(idx & 63);
        int r = (int)(idx >> 6);
        float mu = sums[c] * invn;
        float var = fmaf(-mu, mu, sqs[c] * invn);
        float scl = gam[c] * rsqrtf(var + EPSV);
        float v = fmaxf(fmaf(x[idx] - mu, scl, bet[c]), 0.f);
        atomicMax((unsigned int*)&xp[(size_t)seg[r] * 64 + c], __float_as_uint(v));
    }
}

// final BN apply, float4-vectorized (C=128)
__global__ void __launch_bounds__(256) bn_apply128_v4_kernel(const float* __restrict__ x, float* __restrict__ y,
                                                             int rows,
                                                             const float* __restrict__ gam, const float* __restrict__ bet,
                                                             const float* __restrict__ sums, const float* __restrict__ sqs) {
    size_t total = (size_t)rows * 32;   // float4 groups
    float invn = 1.f / (float)rows;
    for (size_t idx = (size_t)blockIdx.x * 256 + threadIdx.x; idx < total; idx += (size_t)gridDim.x * 256) {
        int c4 = (int)(idx & 31);
        float4 v = ((const float4*)x)[idx];
        float4 sm = ((const float4*)sums)[c4];
        float4 sq = ((const float4*)sqs)[c4];
        float4 gm = ((const float4*)gam)[c4];
        float4 bt = ((const float4*)bet)[c4];
        float mu0 = sm.x * invn, mu1 = sm.y * invn, mu2 = sm.z * invn, mu3 = sm.w * invn;
        float s0 = gm.x * rsqrtf(fmaf(-mu0, mu0, sq.x * invn) + EPSV);
        float s1 = gm.y * rsqrtf(fmaf(-mu1, mu1, sq.y * invn) + EPSV);
        float s2 = gm.z * rsqrtf(fmaf(-mu2, mu2, sq.z * invn) + EPSV);
        float s3 = gm.w * rsqrtf(fmaf(-mu3, mu3, sq.w * invn) + EPSV);
        float4 o;
        o.x = fmaxf(fmaf(v.x - mu0, s0, bt.x), 0.f);
        o.y = fmaxf(fmaf(v.y - mu1, s1, bt.y), 0.f);
        o.z = fmaxf(fmaf(v.z - mu2, s2, bt.z), 0.f);
        o.w = fmaxf(fmaf(v.w - mu3, s3, bt.w), 0.f);
        ((float4*)y)[idx] = o;
    }
}

// ---------------------------------------------------------------- launch
extern "C" void kernel_launch(void* const* d_in, const int* in_sizes, int n_in,
                              void* d_out, int out_size) {
    const float* feats = (const float*)d_in[0];
    const float* W1    = (const float*)d_in[1];
    const float* g1    = (const float*)d_in[3];
    const float* be1   = (const float*)d_in[4];
    const float* W2    = (const float*)d_in[5];
    const float* g2    = (const float*)d_in[7];
    const float* be2   = (const float*)d_in[8];
    const float* W3    = (const float*)d_in[9];
    const float* g3    = (const float*)d_in[11];
    const float* be3   = (const float*)d_in[12];
    const int* km_in   = (const int*)d_in[13];
    const int* km_out  = (const int*)d_in[14];
    const int* seg     = (const int*)d_in[15];
    const int* km2_in  = (const int*)d_in[16];
    const int* km2_out = (const int*)d_in[17];

    int N  = in_sizes[0];
    int M  = in_sizes[13] / 27;
    int M2 = in_sizes[16] / 27;
    int NP = out_size / 128;

    float *x1, *x2, *xp, *y3, *stats; int *nbr, *nbr2;
    cudaGetSymbolAddress((void**)&x1, g_x1);
    cudaGetSymbolAddress((void**)&x2, g_x2);
    cudaGetSymbolAddress((void**)&xp, g_xp);
    cudaGetSymbolAddress((void**)&y3, g_y3);
    cudaGetSymbolAddress((void**)&nbr, g_nbr);
    cudaGetSymbolAddress((void**)&nbr2, g_nbr2);
    cudaGetSymbolAddress((void**)&stats, g_stats);

    constexpr int SM2 = (64 * 128 + 64 * 64) * 8 + 192 * 4;             // 99072
    constexpr int SM3 = 64 * 32 * 8 + 64 * 128 * 4 + 2 * 128 * 4;       // 50176 (R12 config)
    cudaFuncSetAttribute((const void*)conv2_scatter_kernel,
                         cudaFuncAttributeMaxDynamicSharedMemorySize, SM2);
    cudaFuncSetAttribute((const void*)conv3_kernel,
                         cudaFuncAttributeMaxDynamicSharedMemorySize, SM3);

    int initThreads = (N + 1) * 64;
    if (27 * N > initThreads) initThreads = 27 * N;

    // (1) init: stats, sentinel tables, zero xp & x2
    initbig_kernel<<<(initThreads + 255) / 256, 256>>>(nbr, nbr2, xp, x2, stats, N, NP);
    // (2) neighbor table for layer 1 dense gather
    build_nbr_kernel<<<(27 * M + 255) / 256, 256>>>(km_in, km_out, nbr, M, N);
    // (3) conv1 + fused stats1
    conv1_kernel<<<(N + 63) / 64, 256>>>(feats, W1, x1, nbr, N, stats);
    // (4) conv2 scatter, coalesced gather v2     <-- ncu capture target
    {
        dim3 grid((M + 255) / 256, 27);
        conv2_scatter_kernel<<<grid, 256, SM2>>>(
            x1, W2, x2, km_in, km_out, M, N,
            stats + 0, stats + 128, g1, be1, 1.f / (float)N);
    }
    // (5) neighbor table for layer 3
    build_nbr_kernel<<<(27 * M2 + 255) / 256, 256>>>(km2_in, km2_out, nbr2, M2, NP);
    // (6) BN2 stats
    bn_reduce_kernel<64><<<1184, 256>>>(x2, N, stats + 256, stats + 384);
    // (7) BN2+ReLU fused with maxpool
    bn_apply_pool_kernel<<<1184, 256>>>(x2, seg, xp, N, g2, be2, stats + 256, stats + 384);
    // (8) conv3 dense (R12 proven config) + fused stats3
    conv3_kernel<<<(NP + 63) / 64, 256, SM3>>>(
        xp, W3, y3, nbr2, NP, stats + 512, stats + 640);
    // (9) BN3+ReLU -> output (float4 vectorized)
    bn_apply128_v4_kernel<<<1184, 256>>>(y3, (float*)d_out, NP, g3, be3, stats + 512, stats + 640);
}

// round 17
// speedup vs baseline: 1.6101x; 1.0481x over previous
#include <cuda_runtime.h>
#include <cstdint>

#define EPSV 1e-5f
#define N_MAX   163904      // >= N+1 rows (N = 160000)
#define NP_MAX  65792       // >= NPOOL+1 rows

// -------- persistent scratch (no allocs allowed) --------
__device__ float g_x1[(size_t)N_MAX * 64];
__device__ float g_x2[(size_t)N_MAX * 64];
__device__ float g_xp[(size_t)NP_MAX * 64];
__device__ float g_y3[(size_t)NP_MAX * 128];
__device__ int   g_nbr [(size_t)N_MAX * 27];
__device__ int   g_nbr2[(size_t)NP_MAX * 27];
__device__ float g_stats[768];

typedef unsigned long long u64t;

__device__ __forceinline__ u64t pack2(float a, float b) {
    u64t r; unsigned x = __float_as_uint(a), y = __float_as_uint(b);
    asm("mov.b64 %0, {%1, %2};" : "=l"(r) : "r"(x), "r"(y));
    return r;
}
__device__ __forceinline__ void fma2(u64t& d, u64t a, u64t b) {
    asm("fma.rn.f32x2 %0, %1, %2, %0;" : "+l"(d) : "l"(a), "l"(b));
}
__device__ __forceinline__ float2 unpack2(u64t v) {
    unsigned lo, hi; asm("mov.b64 {%0, %1}, %2;" : "=r"(lo), "=r"(hi) : "l"(v));
    return make_float2(__uint_as_float(lo), __uint_as_float(hi));
}
__device__ __forceinline__ void redadd4(float* p, float4 v) {
    asm volatile("red.global.add.v4.f32 [%0], {%1,%2,%3,%4};"
                 :: "l"(p), "f"(v.x), "f"(v.y), "f"(v.z), "f"(v.w) : "memory");
}

// ---------------------------------------------------------------- init (stats, sentinels, zero x2/xp)
__global__ void initbig_kernel(int* __restrict__ nbr, int* __restrict__ nbr2,
                               float* __restrict__ xp, float* __restrict__ x2,
                               float* __restrict__ stats, int N, int NP) {
    int i = blockIdx.x * blockDim.x + threadIdx.x;
    if (i < 768) stats[i] = 0.f;
    if (i < 27 * N) nbr[i] = N;
    if (i < 27 * NP) nbr2[i] = NP;
    if (i < (NP + 1) * 64) xp[i] = 0.f;
    if (i < (N + 1) * 64) x2[i] = 0.f;
}
__global__ void build_nbr_kernel(const int* __restrict__ km_in, const int* __restrict__ km_out,
                                 int* __restrict__ nbr, int M, int Nr) {
    int idx = blockIdx.x * blockDim.x + threadIdx.x;
    if (idx >= 27 * M) return;
    int i = km_in[idx];
    if (i < Nr) {
        int k = idx / M;
        nbr[k * Nr + km_out[idx]] = i;
    }
}

// ---------------------------------------------------------------- conv1: 1 -> 64 channels, fused stats
__global__ void __launch_bounds__(256) conv1_kernel(const float* __restrict__ feats,
                                                    const float* __restrict__ W1,
                                                    float* __restrict__ out,
                                                    const int* __restrict__ nbr, int Nr,
                                                    float* __restrict__ stats) {
    __shared__ float fs[27 * 64];
    __shared__ float ws[27 * 64];
    __shared__ float sh[512];
    int t = threadIdx.x;
    int r0 = blockIdx.x * 64;
    for (int i = t; i < 27 * 64; i += 256) ws[i] = W1[i];
    for (int i = t; i < 27 * 64; i += 256) {
        int k = i >> 6, rr = i & 63, r = r0 + rr;
        float v = 0.f;
        if (r < Nr) {
            int g = nbr[k * Nr + r];
            if (g < Nr) v = feats[g];
        }
        fs[i] = v;
    }
    __syncthreads();
    int c = t & 63, rg = t >> 6;
    float s = 0.f, q = 0.f;
    #pragma unroll
    for (int ri = 0; ri < 16; ri++) {
        int rr = rg * 16 + ri, r = r0 + rr;
        if (r < Nr) {
            float acc = 0.f;
            #pragma unroll
            for (int k = 0; k < 27; k++) acc += fs[k * 64 + rr] * ws[k * 64 + c];
            out[(size_t)r * 64 + c] = acc;
            s += acc; q = fmaf(acc, acc, q);
        }
    }
    sh[t] = s; sh[256 + t] = q;
    __syncthreads();
    if (rg == 0) {
        #pragma unroll
        for (int g = 1; g < 4; g++) { s += sh[g * 64 + c]; q += sh[256 + g * 64 + c]; }
        atomicAdd(&stats[c], s);
        atomicAdd(&stats[128 + c], q);
    }
}

// ---------------------------------------------------------------- conv2: valid-pair scatter GEMM (R16 proven: coalesced gather v2)
__global__ void __launch_bounds__(256, 2) conv2_scatter_kernel(
    const float* __restrict__ x1, const float* __restrict__ W2,
    float* __restrict__ x2,
    const int* __restrict__ km_in, const int* __restrict__ km_out,
    int M, int Nf,
    const float* __restrict__ sums, const float* __restrict__ sqs,
    const float* __restrict__ gam, const float* __restrict__ bet, float invn)
{
    const int k = blockIdx.y;
    const int p0 = blockIdx.x * 256;
    if (__ldg(km_in + (size_t)k * M + p0) >= Nf) return;   // front-packed: all-sentinel chunk

    extern __shared__ char smraw[];
    u64t* Xs = (u64t*)smraw;               // viewed as float[64 ch][256 pairs] (64 KB)
    u64t* Wd = Xs + 64 * 128;              // [64][64] duplicated weights
    float* bnc = (float*)(Wd + 64 * 64);   // mu[64], scl[64], be[64]
    float* Xsf = (float*)Xs;

    const int t = threadIdx.x;
    const int tx = t & 15, ty = t >> 4;

    if (t < 64) {
        float mu = sums[t] * invn;
        float var = fmaf(-mu, mu, sqs[t] * invn);
        bnc[t] = mu;
        bnc[64 + t] = gam[t] * rsqrtf(var + EPSV);
        bnc[128 + t] = bet[t];
    }
    __syncthreads();

    // ---- gather v2: coalesced 8-lanes-per-row, transposed swizzled store
    {
        const int lrow = t & 7;
        const int rgrp = (t >> 3) & 3;
        const int w = t >> 5;
        const uint32_t sw = (uint32_t)(lrow & 3) << 3;
        #pragma unroll
        for (int s = 0; s < 8; s++) {
            int p = s * 32 + w * 4 + rgrp;
            int gp = p0 + p;
            int g = (gp < M) ? __ldg(km_in + (size_t)k * M + gp) : Nf;
            const bool valid = g < Nf;
            const float4* src = (const float4*)(x1 + (size_t)g * 64);
            const int pp = p ^ (int)sw;
            #pragma unroll
            for (int h = 0; h < 2; h++) {
                int q = lrow + h * 8;
                float4 v = make_float4(0.f, 0.f, 0.f, 0.f);
                if (valid) {
                    float4 xv = src[q];
                    float4 mu = ((const float4*)bnc)[q];
                    float4 sc = ((const float4*)(bnc + 64))[q];
                    float4 be = ((const float4*)(bnc + 128))[q];
                    v.x = fmaxf(fmaf(xv.x - mu.x, sc.x, be.x), 0.f);
                    v.y = fmaxf(fmaf(xv.y - mu.y, sc.y, be.y), 0.f);
                    v.z = fmaxf(fmaf(xv.z - mu.z, sc.z, be.z), 0.f);
                    v.w = fmaxf(fmaf(xv.w - mu.w, sc.w, be.w), 0.f);
                }
                int c0 = 4 * q;
                Xsf[(c0 + 0) * 256 + pp] = v.x;
                Xsf[(c0 + 1) * 256 + pp] = v.y;
                Xsf[(c0 + 2) * 256 + pp] = v.z;
                Xsf[(c0 + 3) * 256 + pp] = v.w;
            }
        }
        const float4* wk = (const float4*)(W2 + (size_t)k * 4096);
        #pragma unroll
        for (int i = 0; i < 4; i++) {
            float4 wv = wk[t + i * 256];
            int fi = (t + i * 256) * 4;
            Wd[fi + 0] = pack2(wv.x, wv.x);
            Wd[fi + 1] = pack2(wv.y, wv.y);
            Wd[fi + 2] = pack2(wv.z, wv.z);
            Wd[fi + 3] = pack2(wv.w, wv.w);
        }
    }
    __syncthreads();

    // ---- compute: 64 channels x (8 row-pairs x 4 cols); a-reads deswizzled per j
    u64t acc[8][4];
    #pragma unroll
    for (int i = 0; i < 8; i++)
        #pragma unroll
        for (int c = 0; c < 4; c++) acc[i][c] = 0ULL;

    #pragma unroll 4
    for (int j = 0; j < 64; j++) {
        const uint32_t swj = (uint32_t)((j >> 2) & 3) << 3;
        const u64t* ap1 = (const u64t*)(Xsf + j * 256 + ((ty * 16) ^ swj));
        const u64t* ap2 = (const u64t*)(Xsf + j * 256 + ((ty * 16 + 8) ^ swj));
        const u64t* bp = Wd + j * 64 + tx * 4;
        u64t a0 = ap1[0], a1 = ap1[1], a2 = ap1[2], a3 = ap1[3];
        u64t a4 = ap2[0], a5 = ap2[1], a6 = ap2[2], a7 = ap2[3];
        u64t b0 = bp[0], b1 = bp[1], b2 = bp[2], b3 = bp[3];
        fma2(acc[0][0], a0, b0); fma2(acc[0][1], a0, b1); fma2(acc[0][2], a0, b2); fma2(acc[0][3], a0, b3);
        fma2(acc[1][0], a1, b0); fma2(acc[1][1], a1, b1); fma2(acc[1][2], a1, b2); fma2(acc[1][3], a1, b3);
        fma2(acc[2][0], a2, b0); fma2(acc[2][1], a2, b1); fma2(acc[2][2], a2, b2); fma2(acc[2][3], a2, b3);
        fma2(acc[3][0], a3, b0); fma2(acc[3][1], a3, b1); fma2(acc[3][2], a3, b2); fma2(acc[3][3], a3, b3);
        fma2(acc[4][0], a4, b0); fma2(acc[4][1], a4, b1); fma2(acc[4][2], a4, b2); fma2(acc[4][3], a4, b3);
        fma2(acc[5][0], a5, b0); fma2(acc[5][1], a5, b1); fma2(acc[5][2], a5, b2); fma2(acc[5][3], a5, b3);
        fma2(acc[6][0], a6, b0); fma2(acc[6][1], a6, b1); fma2(acc[6][2], a6, b2); fma2(acc[6][3], a6, b3);
        fma2(acc[7][0], a7, b0); fma2(acc[7][1], a7, b1); fma2(acc[7][2], a7, b2); fma2(acc[7][3], a7, b3);
    }

    // ---- scatter epilogue: v4 vector reds, skip sentinels
    #pragma unroll
    for (int i = 0; i < 8; i++) {
        int pr = p0 + ty * 16 + 2 * i;
        int oa = (pr < M) ? __ldg(km_out + (size_t)k * M + pr) : Nf;
        int ob = (pr + 1 < M) ? __ldg(km_out + (size_t)k * M + pr + 1) : Nf;
        float2 e0 = unpack2(acc[i][0]), e1 = unpack2(acc[i][1]);
        float2 e2 = unpack2(acc[i][2]), e3 = unpack2(acc[i][3]);
        if (oa < Nf)
            redadd4(x2 + (size_t)oa * 64 + tx * 4, make_float4(e0.x, e1.x, e2.x, e3.x));
        if (ob < Nf)
            redadd4(x2 + (size_t)ob * 64 + tx * 4, make_float4(e0.y, e1.y, e2.y, e3.y));
    }
}

// ---------------------------------------------------------------- conv3: dense gather, 3 CTAs/SM, coalesced gather v2
// 8 lanes/row gather (4 wavefronts/instr), transposed swizzled store Xsf[ch][row],
// compute deswizzles via compile-time pair-slot permutation i^((j>>2)&3).
__global__ void __launch_bounds__(256, 3) conv3_kernel(
    const float* __restrict__ x, const float* __restrict__ W,
    float* __restrict__ out, const int* __restrict__ nbr, int Nr,
    float* __restrict__ oS, float* __restrict__ oQ)
{
    extern __shared__ char smraw[];
    float* Xsf = (float*)smraw;           // [64 ch][64 rows] transposed (16 KB)
    float* Ws = Xsf + 64 * 64;            // [64 j][128 c] plain floats (32 KB)
    float* redS = Ws + 64 * 128;
    float* redQ = redS + 128;

    const int t = threadIdx.x;
    const int tx = t & 31, ty = t >> 5;   // warp-uniform ty
    const int r0 = blockIdx.x * 64;
    const int w = t >> 5;
    const int lane8 = t & 7;
    const int rgrp = (t >> 3) & 3;

    if (t < 128) { redS[t] = 0.f; redQ[t] = 0.f; }

    u64t acc[4][4];
    #pragma unroll
    for (int i = 0; i < 4; i++)
        #pragma unroll
        for (int c = 0; c < 4; c++) acc[i][c] = 0ULL;

    // two passes: pass s covers rows s*32 + w*4 + rgrp
    const int row0 = 0 * 32 + w * 4 + rgrp;
    const int row1 = 1 * 32 + w * 4 + rgrp;

    float4 xpre[4];   // pass0: xpre[0..1] (h=0,1); pass1: xpre[2..3]

    auto ldg_x = [&](int k) {
        int g0 = (r0 + row0 < Nr) ? __ldg(nbr + (size_t)k * Nr + r0 + row0) : Nr;
        int g1 = (r0 + row1 < Nr) ? __ldg(nbr + (size_t)k * Nr + r0 + row1) : Nr;
        const float4* s0 = (const float4*)(x + (size_t)g0 * 64);
        const float4* s1 = (const float4*)(x + (size_t)g1 * 64);
        xpre[0] = s0[lane8];      // h=0: q = lane8
        xpre[1] = s0[8 + lane8];  // h=1
        xpre[2] = s1[lane8];
        xpre[3] = s1[8 + lane8];
    };

    ldg_x(0);   // prologue

    for (int k = 0; k < 27; k++) {
        __syncthreads();    // previous compute done; Xsf/Ws free
        // STS prefetched X: transposed, row-swizzled (xor preserves pair adjacency)
        #pragma unroll
        for (int s = 0; s < 2; s++) {
            const int row = (s == 0) ? row0 : row1;
            #pragma unroll
            for (int h = 0; h < 2; h++) {
                float4 v = xpre[2 * s + h];
                int jgrp = h * 8 + lane8;                 // channel-group 0..15
                int c0 = 4 * jgrp;
                int rowp = row ^ ((jgrp & 3) << 1);
                Xsf[(c0 + 0) * 64 + rowp] = v.x;
                Xsf[(c0 + 1) * 64 + rowp] = v.y;
                Xsf[(c0 + 2) * 64 + rowp] = v.z;
                Xsf[(c0 + 3) * 64 + rowp] = v.w;
            }
        }
        // W tile: plain float4 copy
        const float4* wk = (const float4*)(W + (size_t)k * 8192);
        #pragma unroll
        for (int i = 0; i < 8; i++)
            ((float4*)Ws)[t + i * 256] = wk[t + i * 256];
        __syncthreads();

        if (k < 26) ldg_x(k + 1);   // gather chain for k+1 under compute(k)

        #pragma unroll
        for (int j = 0; j < 64; j++) {
            const int x2p = (j >> 2) & 3;                 // compile-time in unrolled loop
            const u64t* qp = (const u64t*)(Xsf + j * 64 + ty * 8);
            u64t q0 = qp[0], q1 = qp[1], q2 = qp[2], q3 = qp[3];
            u64t a0 = (x2p == 0) ? q0 : (x2p == 1) ? q1 : (x2p == 2) ? q2 : q3;
            u64t a1 = (x2p == 0) ? q1 : (x2p == 1) ? q0 : (x2p == 2) ? q3 : q2;
            u64t a2 = (x2p == 0) ? q2 : (x2p == 1) ? q3 : (x2p == 2) ? q0 : q1;
            u64t a3 = (x2p == 0) ? q3 : (x2p == 1) ? q2 : (x2p == 2) ? q1 : q0;
            float4 bw = ((const float4*)(Ws + j * 128))[tx];
            u64t b0 = pack2(bw.x, bw.x), b1 = pack2(bw.y, bw.y);
            u64t b2 = pack2(bw.z, bw.z), b3 = pack2(bw.w, bw.w);
            fma2(acc[0][0], a0, b0); fma2(acc[0][1], a0, b1); fma2(acc[0][2], a0, b2); fma2(acc[0][3], a0, b3);
            fma2(acc[1][0], a1, b0); fma2(acc[1][1], a1, b1); fma2(acc[1][2], a1, b2); fma2(acc[1][3], a1, b3);
            fma2(acc[2][0], a2, b0); fma2(acc[2][1], a2, b1); fma2(acc[2][2], a2, b2); fma2(acc[2][3], a2, b3);
            fma2(acc[3][0], a3, b0); fma2(acc[3][1], a3, b1); fma2(acc[3][2], a3, b2); fma2(acc[3][3], a3, b3);
        }
    }

    // ---- epilogue: store + fused BN stats partials (rows ty*8+2i / +1)
    float scol[4] = {0.f, 0.f, 0.f, 0.f}, qcol[4] = {0.f, 0.f, 0.f, 0.f};
    #pragma unroll
    for (int i = 0; i < 4; i++) {
        float2 e0 = unpack2(acc[i][0]), e1 = unpack2(acc[i][1]);
        float2 e2 = unpack2(acc[i][2]), e3 = unpack2(acc[i][3]);
        int re = r0 + ty * 8 + 2 * i;
        if (re < Nr) {
            *(float4*)(out + (size_t)re * 128 + tx * 4) = make_float4(e0.x, e1.x, e2.x, e3.x);
            scol[0] += e0.x; qcol[0] = fmaf(e0.x, e0.x, qcol[0]);
            scol[1] += e1.x; qcol[1] = fmaf(e1.x, e1.x, qcol[1]);
            scol[2] += e2.x; qcol[2] = fmaf(e2.x, e2.x, qcol[2]);
            scol[3] += e3.x; qcol[3] = fmaf(e3.x, e3.x, qcol[3]);
        }
        if (re + 1 < Nr) {
            *(float4*)(out + (size_t)(re + 1) * 128 + tx * 4) = make_float4(e0.y, e1.y, e2.y, e3.y);
            scol[0] += e0.y; qcol[0] = fmaf(e0.y, e0.y, qcol[0]);
            scol[1] += e1.y; qcol[1] = fmaf(e1.y, e1.y, qcol[1]);
            scol[2] += e2.y; qcol[2] = fmaf(e2.y, e2.y, qcol[2]);
            scol[3] += e3.y; qcol[3] = fmaf(e3.y, e3.y, qcol[3]);
        }
    }
    __syncthreads();
    #pragma unroll
    for (int c = 0; c < 4; c++) {
        atomicAdd(&redS[tx * 4 + c], scol[c]);
        atomicAdd(&redQ[tx * 4 + c], qcol[c]);
    }
    __syncthreads();
    if (t < 128) {
        atomicAdd(&oS[t], redS[t]);
        atomicAdd(&oQ[t], redQ[t]);
    }
}

// ---------------------------------------------------------------- BN reduce / apply / pool
template<int C>
__global__ void __launch_bounds__(256) bn_reduce_kernel(const float* __restrict__ x, int rows,
                                                        float* __restrict__ sumo, float* __restrict__ sqo) {
    constexpr int G = 256 / C;
    int t = threadIdx.x, c = t & (C - 1), rg = t / C;
    float s = 0.f, q = 0.f;
    for (int r = blockIdx.x * G + rg; r < rows; r += gridDim.x * G) {
        float v = x[(size_t)r * C + c];
        s += v; q = fmaf(v, v, q);
    }
    __shared__ float sh[512];
    sh[t] = s; sh[256 + t] = q;
    __syncthreads();
    if (rg == 0) {
        #pragma unroll
        for (int g = 1; g < G; g++) { s += sh[g * C + c]; q += sh[256 + g * C + c]; }
        atomicAdd(&sumo[c], s);
        atomicAdd(&sqo[c], q);
    }
}

__global__ void __launch_bounds__(256) bn_apply_pool_kernel(const float* __restrict__ x,
                                                            const int* __restrict__ seg,
                                                            float* __restrict__ xp, int rows,
                                                            const float* __restrict__ gam, const float* __restrict__ bet,
                                                            const float* __restrict__ sums, const float* __restrict__ sqs) {
    size_t total = (size_t)rows * 64;
    float invn = 1.f / (float)rows;
    for (size_t idx = (size_t)blockIdx.x * 256 + threadIdx.x; idx < total; idx += (size_t)gridDim.x * 256) {
        int c = (int)(idx & 63);
        int r = (int)(idx >> 6);
        float mu = sums[c] * invn;
        float var = fmaf(-mu, mu, sqs[c] * invn);
        float scl = gam[c] * rsqrtf(var + EPSV);
        float v = fmaxf(fmaf(x[idx] - mu, scl, bet[c]), 0.f);
        atomicMax((unsigned int*)&xp[(size_t)seg[r] * 64 + c], __float_as_uint(v));
    }
}

// final BN apply, float4-vectorized (C=128)
__global__ void __launch_bounds__(256) bn_apply128_v4_kernel(const float* __restrict__ x, float* __restrict__ y,
                                                             int rows,
                                                             const float* __restrict__ gam, const float* __restrict__ bet,
                                                             const float* __restrict__ sums, const float* __restrict__ sqs) {
    size_t total = (size_t)rows * 32;   // float4 groups
    float invn = 1.f / (float)rows;
    for (size_t idx = (size_t)blockIdx.x * 256 + threadIdx.x; idx < total; idx += (size_t)gridDim.x * 256) {
        int c4 = (int)(idx & 31);
        float4 v = ((const float4*)x)[idx];
        float4 sm = ((const float4*)sums)[c4];
        float4 sq = ((const float4*)sqs)[c4];
        float4 gm = ((const float4*)gam)[c4];
        float4 bt = ((const float4*)bet)[c4];
        float mu0 = sm.x * invn, mu1 = sm.y * invn, mu2 = sm.z * invn, mu3 = sm.w * invn;
        float s0 = gm.x * rsqrtf(fmaf(-mu0, mu0, sq.x * invn) + EPSV);
        float s1 = gm.y * rsqrtf(fmaf(-mu1, mu1, sq.y * invn) + EPSV);
        float s2 = gm.z * rsqrtf(fmaf(-mu2, mu2, sq.z * invn) + EPSV);
        float s3 = gm.w * rsqrtf(fmaf(-mu3, mu3, sq.w * invn) + EPSV);
        float4 o;
        o.x = fmaxf(fmaf(v.x - mu0, s0, bt.x), 0.f);
        o.y = fmaxf(fmaf(v.y - mu1, s1, bt.y), 0.f);
        o.z = fmaxf(fmaf(v.z - mu2, s2, bt.z), 0.f);
        o.w = fmaxf(fmaf(v.w - mu3, s3, bt.w), 0.f);
        ((float4*)y)[idx] = o;
    }
}

// ---------------------------------------------------------------- launch
extern "C" void kernel_launch(void* const* d_in, const int* in_sizes, int n_in,
                              void* d_out, int out_size) {
    const float* feats = (const float*)d_in[0];
    const float* W1    = (const float*)d_in[1];
    const float* g1    = (const float*)d_in[3];
    const float* be1   = (const float*)d_in[4];
    const float* W2    = (const float*)d_in[5];
    const float* g2    = (const float*)d_in[7];
    const float* be2   = (const float*)d_in[8];
    const float* W3    = (const float*)d_in[9];
    const float* g3    = (const float*)d_in[11];
    const float* be3   = (const float*)d_in[12];
    const int* km_in   = (const int*)d_in[13];
    const int* km_out  = (const int*)d_in[14];
    const int* seg     = (const int*)d_in[15];
    const int* km2_in  = (const int*)d_in[16];
    const int* km2_out = (const int*)d_in[17];

    int N  = in_sizes[0];
    int M  = in_sizes[13] / 27;
    int M2 = in_sizes[16] / 27;
    int NP = out_size / 128;

    float *x1, *x2, *xp, *y3, *stats; int *nbr, *nbr2;
    cudaGetSymbolAddress((void**)&x1, g_x1);
    cudaGetSymbolAddress((void**)&x2, g_x2);
    cudaGetSymbolAddress((void**)&xp, g_xp);
    cudaGetSymbolAddress((void**)&y3, g_y3);
    cudaGetSymbolAddress((void**)&nbr, g_nbr);
    cudaGetSymbolAddress((void**)&nbr2, g_nbr2);
    cudaGetSymbolAddress((void**)&stats, g_stats);

    constexpr int SM2 = (64 * 128 + 64 * 64) * 8 + 192 * 4;             // 99072
    constexpr int SM3 = 64 * 64 * 4 + 64 * 128 * 4 + 2 * 128 * 4;       // 50176
    cudaFuncSetAttribute((const void*)conv2_scatter_kernel,
                         cudaFuncAttributeMaxDynamicSharedMemorySize, SM2);
    cudaFuncSetAttribute((const void*)conv3_kernel,
                         cudaFuncAttributeMaxDynamicSharedMemorySize, SM3);

    int initThreads = (N + 1) * 64;
    if (27 * N > initThreads) initThreads = 27 * N;

    // (1) init: stats, sentinel tables, zero xp & x2
    initbig_kernel<<<(initThreads + 255) / 256, 256>>>(nbr, nbr2, xp, x2, stats, N, NP);
    // (2) neighbor table for layer 1 dense gather
    build_nbr_kernel<<<(27 * M + 255) / 256, 256>>>(km_in, km_out, nbr, M, N);
    // (3) conv1 + fused stats1
    conv1_kernel<<<(N + 63) / 64, 256>>>(feats, W1, x1, nbr, N, stats);
    // (4) conv2 scatter, coalesced gather v2     <-- ncu capture target
    {
        dim3 grid((M + 255) / 256, 27);
        conv2_scatter_kernel<<<grid, 256, SM2>>>(
            x1, W2, x2, km_in, km_out, M, N,
            stats + 0, stats + 128, g1, be1, 1.f / (float)N);
    }
    // (5) neighbor table for layer 3
    build_nbr_kernel<<<(27 * M2 + 255) / 256, 256>>>(km2_in, km2_out, nbr2, M2, NP);
    // (6) BN2 stats
    bn_reduce_kernel<64><<<1184, 256>>>(x2, N, stats + 256, stats + 384);
    // (7) BN2+ReLU fused with maxpool
    bn_apply_pool_kernel<<<1184, 256>>>(x2, seg, xp, N, g2, be2, stats + 256, stats + 384);
    // (8) conv3 dense, coalesced gather v2, 3 CTAs/SM + fused stats3
    conv3_kernel<<<(NP + 63) / 64, 256, SM3>>>(
        xp, W3, y3, nbr2, NP, stats + 512, stats + 640);
    // (9) BN3+ReLU -> output (float4 vectorized)
    bn_apply128_v4_kernel<<<1184, 256>>>(y3, (float*)d_out, NP, g3, be3, stats + 512, stats + 640);
}